// round 3
// baseline (speedup 1.0000x reference)
#include <cuda_runtime.h>
#include <cstdint>

#define B_ 2
#define S_ 2048
#define D_ 1024
#define H_ 16
#define DH_ 64
#define NG_ 204
#define SCALE_ 0.125f

// ---------------- scratch (static device globals; no allocations) ----------------
__device__ float g_Q[B_ * H_ * S_ * DH_];
__device__ float g_K[B_ * H_ * S_ * DH_];
__device__ float g_V[B_ * H_ * S_ * DH_];
__device__ float g_local[B_ * H_ * S_ * DH_];
__device__ float g_glob[B_ * H_ * S_ * DH_];
__device__ float g_fused[B_ * S_ * D_];
__device__ int   g_topk[B_ * H_ * NG_];

// ---------------- QKV projection GEMM: [4096,1024] @ [1024,1024], scatter to [b,h,s,d] ----------------
// 64x64 block tile, BK=16, 256 threads, 4x4 microtile.
__global__ void qkv_gemm(const float* __restrict__ x,
                         const float* __restrict__ Wq,
                         const float* __restrict__ Wk,
                         const float* __restrict__ Wv) {
    __shared__ float As[16][65];   // A^T tile
    __shared__ float Bs[16][64];

    const float* W;
    float* C;
    if (blockIdx.z == 0)      { W = Wq; C = g_Q; }
    else if (blockIdx.z == 1) { W = Wk; C = g_K; }
    else                      { W = Wv; C = g_V; }

    const int tid = threadIdx.x;
    const int tx = tid & 15, ty = tid >> 4;
    const int m0 = blockIdx.y * 64, n0 = blockIdx.x * 64;
    const int arow = tid >> 2, ac = (tid & 3) << 2;
    const int brow = tid >> 4, bc = (tid & 15) << 2;

    float acc[4][4] = {};

    for (int k0 = 0; k0 < D_; k0 += 16) {
        float4 av = *(const float4*)(x + (size_t)(m0 + arow) * D_ + k0 + ac);
        As[ac + 0][arow] = av.x;
        As[ac + 1][arow] = av.y;
        As[ac + 2][arow] = av.z;
        As[ac + 3][arow] = av.w;
        *(float4*)&Bs[brow][bc] =
            *(const float4*)(W + (size_t)(k0 + brow) * D_ + n0 + bc);
        __syncthreads();
#pragma unroll
        for (int kk = 0; kk < 16; kk++) {
            float a[4], b[4];
#pragma unroll
            for (int i = 0; i < 4; i++) a[i] = As[kk][ty * 4 + i];
#pragma unroll
            for (int j = 0; j < 4; j++) b[j] = Bs[kk][tx * 4 + j];
#pragma unroll
            for (int i = 0; i < 4; i++)
#pragma unroll
                for (int j = 0; j < 4; j++) acc[i][j] += a[i] * b[j];
        }
        __syncthreads();
    }

#pragma unroll
    for (int i = 0; i < 4; i++) {
        int m = m0 + ty * 4 + i;
        int bb = m / S_, ss = m % S_;
#pragma unroll
        for (int j = 0; j < 4; j++) {
            int n = n0 + tx * 4 + j;
            int h = n >> 6, d = n & 63;
            C[(((size_t)(bb * H_ + h) * S_) + ss) * DH_ + d] = acc[i][j];
        }
    }
}

// ---------------- top-k by key norm: one block per (b,h), bitonic sort in SMEM ----------------
__global__ void topk_kernel() {
    __shared__ float nrm[S_];
    __shared__ int   ind[S_];
    const int bh = blockIdx.x;
    const float* Kp = g_K + (size_t)bh * S_ * DH_;

    for (int s = threadIdx.x; s < S_; s += blockDim.x) {
        const float* kr = Kp + s * DH_;
        float sum = 0.f;
#pragma unroll 8
        for (int d = 0; d < DH_; d++) { float v = kr[d]; sum += v * v; }
        nrm[s] = sum;   // squared norm; monotone in norm
        ind[s] = s;
    }
    __syncthreads();

    // ascending bitonic sort
    for (int k = 2; k <= S_; k <<= 1) {
        for (int j = k >> 1; j > 0; j >>= 1) {
            for (int t = threadIdx.x; t < S_; t += blockDim.x) {
                int ixj = t ^ j;
                if (ixj > t) {
                    float a = nrm[t], b = nrm[ixj];
                    bool sw = ((t & k) == 0) ? (a > b) : (a < b);
                    if (sw) {
                        nrm[t] = b; nrm[ixj] = a;
                        int ti = ind[t]; ind[t] = ind[ixj]; ind[ixj] = ti;
                    }
                }
            }
            __syncthreads();
        }
    }
    // largest NG_ are at the tail
    for (int g = threadIdx.x; g < NG_; g += blockDim.x)
        g_topk[bh * NG_ + g] = ind[S_ - NG_ + g];
}

// ---------------- flash-style attention helpers ----------------
#define FL_QS   (64 * 64)
#define FL_KS   (64 * 65)
#define FL_VS   (64 * 64)
#define FL_SMEM ((FL_QS + FL_KS + FL_VS) * 4)

__device__ __forceinline__ float red_max16(float v) {
#pragma unroll
    for (int off = 8; off > 0; off >>= 1)
        v = fmaxf(v, __shfl_xor_sync(0xffffffffu, v, off, 16));
    return v;
}
__device__ __forceinline__ float red_sum16(float v) {
#pragma unroll
    for (int off = 8; off > 0; off >>= 1)
        v += __shfl_xor_sync(0xffffffffu, v, off, 16);
    return v;
}

// ---------------- local (full) attention ----------------
__global__ void flash_local() {
    extern __shared__ float sm[];
    float* Qs = sm;            // [64][64]
    float* Ks = sm + FL_QS;    // [64][65], reused as P after scores
    float* Vs = Ks + FL_KS;    // [64][64]

    const int bh = blockIdx.y;
    const int q0 = blockIdx.x * 64;
    const int tid = threadIdx.x;
    const int tx = tid & 15, ty = tid >> 4;

    const float* Qp = g_Q + ((size_t)bh * S_ + q0) * DH_;
    const float* Kp = g_K + (size_t)bh * S_ * DH_;
    const float* Vp = g_V + (size_t)bh * S_ * DH_;

    for (int i2 = tid; i2 < 4096; i2 += 256) Qs[i2] = Qp[i2];

    float acc[4][4] = {};
    float mrow[4] = {-1e30f, -1e30f, -1e30f, -1e30f};
    float lrow[4] = {0.f, 0.f, 0.f, 0.f};

    for (int kt = 0; kt < S_ / 64; kt++) {
        __syncthreads();   // previous tile fully consumed
        const float* Kt = Kp + (size_t)kt * 64 * DH_;
        const float* Vt = Vp + (size_t)kt * 64 * DH_;
        for (int i2 = tid; i2 < 4096; i2 += 256) {
            int r = i2 >> 6, c = i2 & 63;
            Ks[r * 65 + c] = Kt[i2];
            Vs[i2] = Vt[i2];
        }
        __syncthreads();

        float s[4][4] = {};
#pragma unroll 8
        for (int d = 0; d < 64; d++) {
            float a[4], b[4];
#pragma unroll
            for (int i = 0; i < 4; i++) a[i] = Qs[(ty * 4 + i) * 64 + d];
#pragma unroll
            for (int j = 0; j < 4; j++) b[j] = Ks[(tx * 4 + j) * 65 + d];
#pragma unroll
            for (int i = 0; i < 4; i++)
#pragma unroll
                for (int j = 0; j < 4; j++) s[i][j] += a[i] * b[j];
        }

#pragma unroll
        for (int i = 0; i < 4; i++) {
            float mx = -1e30f;
#pragma unroll
            for (int j = 0; j < 4; j++) { s[i][j] *= SCALE_; mx = fmaxf(mx, s[i][j]); }
            mx = red_max16(mx);
            float mnew = fmaxf(mrow[i], mx);
            float corr = __expf(mrow[i] - mnew);
            mrow[i] = mnew;
            float ls = 0.f;
#pragma unroll
            for (int j = 0; j < 4; j++) { s[i][j] = __expf(s[i][j] - mnew); ls += s[i][j]; }
            ls = red_sum16(ls);
            lrow[i] = lrow[i] * corr + ls;
#pragma unroll
            for (int j = 0; j < 4; j++) acc[i][j] *= corr;
        }

        __syncthreads();   // everyone done reading Ks before overwrite with P
#pragma unroll
        for (int i = 0; i < 4; i++)
#pragma unroll
            for (int j = 0; j < 4; j++)
                Ks[(ty * 4 + i) * 65 + tx * 4 + j] = s[i][j];
        __syncthreads();

#pragma unroll 8
        for (int c = 0; c < 64; c++) {
            float p[4], v[4];
#pragma unroll
            for (int i = 0; i < 4; i++) p[i] = Ks[(ty * 4 + i) * 65 + c];
#pragma unroll
            for (int j = 0; j < 4; j++) v[j] = Vs[c * 64 + tx * 4 + j];
#pragma unroll
            for (int i = 0; i < 4; i++)
#pragma unroll
                for (int j = 0; j < 4; j++) acc[i][j] += p[i] * v[j];
        }
    }

    float* Op = g_local + ((size_t)bh * S_ + q0) * DH_;
#pragma unroll
    for (int i = 0; i < 4; i++) {
        float inv = 1.f / lrow[i];
#pragma unroll
        for (int j = 0; j < 4; j++)
            Op[(ty * 4 + i) * 64 + tx * 4 + j] = acc[i][j] * inv;
    }
}

// ---------------- global (top-k gathered) attention + per-head LayerNorm ----------------
__global__ void flash_global(const float* __restrict__ gamma,
                             const float* __restrict__ beta) {
    extern __shared__ float sm[];
    float* Qs = sm;
    float* Ks = sm + FL_QS;
    float* Vs = Ks + FL_KS;

    const int bh = blockIdx.y;
    const int q0 = blockIdx.x * 64;
    const int tid = threadIdx.x;
    const int tx = tid & 15, ty = tid >> 4;

    const float* Qp = g_Q + ((size_t)bh * S_ + q0) * DH_;
    const float* Kp = g_K + (size_t)bh * S_ * DH_;
    const float* Vp = g_V + (size_t)bh * S_ * DH_;
    const int*   tk = g_topk + bh * NG_;

    for (int i2 = tid; i2 < 4096; i2 += 256) Qs[i2] = Qp[i2];

    float acc[4][4] = {};
    float mrow[4] = {-1e30f, -1e30f, -1e30f, -1e30f};
    float lrow[4] = {0.f, 0.f, 0.f, 0.f};

    const int NT = (NG_ + 63) / 64;   // 4 tiles
    for (int kt = 0; kt < NT; kt++) {
        __syncthreads();
        for (int i2 = tid; i2 < 4096; i2 += 256) {
            int r = i2 >> 6, c = i2 & 63;
            int gc = kt * 64 + r;
            float kv = 0.f, vv = 0.f;
            if (gc < NG_) {
                int ki = tk[gc];
                kv = Kp[(size_t)ki * DH_ + c];
                vv = Vp[(size_t)ki * DH_ + c];
            }
            Ks[r * 65 + c] = kv;
            Vs[i2] = vv;
        }
        __syncthreads();

        float s[4][4] = {};
#pragma unroll 8
        for (int d = 0; d < 64; d++) {
            float a[4], b[4];
#pragma unroll
            for (int i = 0; i < 4; i++) a[i] = Qs[(ty * 4 + i) * 64 + d];
#pragma unroll
            for (int j = 0; j < 4; j++) b[j] = Ks[(tx * 4 + j) * 65 + d];
#pragma unroll
            for (int i = 0; i < 4; i++)
#pragma unroll
                for (int j = 0; j < 4; j++) s[i][j] += a[i] * b[j];
        }

#pragma unroll
        for (int i = 0; i < 4; i++) {
            float mx = -1e30f;
#pragma unroll
            for (int j = 0; j < 4; j++) {
                s[i][j] *= SCALE_;
                if (kt * 64 + tx * 4 + j >= NG_) s[i][j] = -1e30f;
                mx = fmaxf(mx, s[i][j]);
            }
            mx = red_max16(mx);
            float mnew = fmaxf(mrow[i], mx);
            float corr = __expf(mrow[i] - mnew);
            mrow[i] = mnew;
            float ls = 0.f;
#pragma unroll
            for (int j = 0; j < 4; j++) { s[i][j] = __expf(s[i][j] - mnew); ls += s[i][j]; }
            ls = red_sum16(ls);
            lrow[i] = lrow[i] * corr + ls;
#pragma unroll
            for (int j = 0; j < 4; j++) acc[i][j] *= corr;
        }

        __syncthreads();
#pragma unroll
        for (int i = 0; i < 4; i++)
#pragma unroll
            for (int j = 0; j < 4; j++)
                Ks[(ty * 4 + i) * 65 + tx * 4 + j] = s[i][j];
        __syncthreads();

#pragma unroll 8
        for (int c = 0; c < 64; c++) {
            float p[4], v[4];
#pragma unroll
            for (int i = 0; i < 4; i++) p[i] = Ks[(ty * 4 + i) * 65 + c];
#pragma unroll
            for (int j = 0; j < 4; j++) v[j] = Vs[c * 64 + tx * 4 + j];
#pragma unroll
            for (int i = 0; i < 4; i++)
#pragma unroll
                for (int j = 0; j < 4; j++) acc[i][j] += p[i] * v[j];
        }
    }

    // epilogue: divide by l, per-row LayerNorm over DH=64, write g_glob
    float* Op = g_glob + ((size_t)bh * S_ + q0) * DH_;
#pragma unroll
    for (int i = 0; i < 4; i++) {
        float v[4];
        float linv = 1.f / lrow[i];
#pragma unroll
        for (int j = 0; j < 4; j++) v[j] = acc[i][j] * linv;
        float mu = v[0] + v[1] + v[2] + v[3];
        mu = red_sum16(mu) * (1.f / 64.f);
        float var = 0.f;
#pragma unroll
        for (int j = 0; j < 4; j++) { float t = v[j] - mu; var += t * t; }
        var = red_sum16(var) * (1.f / 64.f);
        float inv = rsqrtf(var + 1e-5f);
#pragma unroll
        for (int j = 0; j < 4; j++) {
            int c = tx * 4 + j;
            Op[(ty * 4 + i) * 64 + c] = (v[j] - mu) * inv * gamma[c] + beta[c];
        }
    }
}

// ---------------- gate: sigmoid([local, global] @ Wg + bg), fuse, repack to [b,s,h*d] ----------------
__global__ void gate_kernel(const float* __restrict__ Wg,
                            const float* __restrict__ bg) {
    __shared__ float Wgs[128 * 64];   // 32 KB
    __shared__ float sloc[4][64];
    __shared__ float sglob[4][64];

    const int tid = threadIdx.x;
    for (int i = tid; i < 128 * 64; i += 256) Wgs[i] = Wg[i];

    const int r0 = blockIdx.x * 4;
    const int rs = tid >> 6;      // row within block (0..3)
    const int j  = tid & 63;      // output column
    const int r  = r0 + rs;       // row in [b,h,s] order

    sloc[rs][j]  = g_local[(size_t)r * 64 + j];
    sglob[rs][j] = g_glob[(size_t)r * 64 + j];
    __syncthreads();

    float acc = bg[j];
#pragma unroll 8
    for (int k = 0; k < 64; k++)
        acc += sloc[rs][k] * Wgs[k * 64 + j] + sglob[rs][k] * Wgs[(64 + k) * 64 + j];

    float g = 1.f / (1.f + __expf(-acc));
    float fused = g * sloc[rs][j] + (1.f - g) * sglob[rs][j];

    int bb = r / (H_ * S_);
    int h  = (r / S_) % H_;
    int ss = r % S_;
    g_fused[((size_t)bb * S_ + ss) * D_ + h * DH_ + j] = fused;
}

// ---------------- output projection: fused [4096,1024] @ Wo [1024,1024] + bo ----------------
__global__ void out_gemm(const float* __restrict__ Wo,
                         const float* __restrict__ bo,
                         float* __restrict__ out) {
    __shared__ float As[16][65];
    __shared__ float Bs[16][64];

    const int tid = threadIdx.x;
    const int tx = tid & 15, ty = tid >> 4;
    const int m0 = blockIdx.y * 64, n0 = blockIdx.x * 64;
    const int arow = tid >> 2, ac = (tid & 3) << 2;
    const int brow = tid >> 4, bc = (tid & 15) << 2;

    float acc[4][4] = {};

    for (int k0 = 0; k0 < D_; k0 += 16) {
        float4 av = *(const float4*)(g_fused + (size_t)(m0 + arow) * D_ + k0 + ac);
        As[ac + 0][arow] = av.x;
        As[ac + 1][arow] = av.y;
        As[ac + 2][arow] = av.z;
        As[ac + 3][arow] = av.w;
        *(float4*)&Bs[brow][bc] =
            *(const float4*)(Wo + (size_t)(k0 + brow) * D_ + n0 + bc);
        __syncthreads();
#pragma unroll
        for (int kk = 0; kk < 16; kk++) {
            float a[4], b[4];
#pragma unroll
            for (int i = 0; i < 4; i++) a[i] = As[kk][ty * 4 + i];
#pragma unroll
            for (int j = 0; j < 4; j++) b[j] = Bs[kk][tx * 4 + j];
#pragma unroll
            for (int i = 0; i < 4; i++)
#pragma unroll
                for (int j = 0; j < 4; j++) acc[i][j] += a[i] * b[j];
        }
        __syncthreads();
    }

#pragma unroll
    for (int i = 0; i < 4; i++) {
        int m = m0 + ty * 4 + i;
#pragma unroll
        for (int j = 0; j < 4; j++) {
            int n = n0 + tx * 4 + j;
            out[(size_t)m * D_ + n] = acc[i][j] + bo[n];
        }
    }
}

// ---------------- launch ----------------
extern "C" void kernel_launch(void* const* d_in, const int* in_sizes, int n_in,
                              void* d_out, int out_size) {
    (void)in_sizes; (void)n_in; (void)out_size;
    const float* x   = (const float*)d_in[0];
    const float* Wq  = (const float*)d_in[1];
    const float* Wk  = (const float*)d_in[2];
    const float* Wv  = (const float*)d_in[3];
    const float* Wo  = (const float*)d_in[4];
    const float* bo  = (const float*)d_in[5];
    const float* gam = (const float*)d_in[6];
    const float* bet = (const float*)d_in[7];
    const float* Wg  = (const float*)d_in[8];
    const float* bg  = (const float*)d_in[9];
    float* out = (float*)d_out;

    cudaFuncSetAttribute(flash_local,  cudaFuncAttributeMaxDynamicSharedMemorySize, FL_SMEM);
    cudaFuncSetAttribute(flash_global, cudaFuncAttributeMaxDynamicSharedMemorySize, FL_SMEM);

    qkv_gemm<<<dim3(D_ / 64, (B_ * S_) / 64, 3), 256>>>(x, Wq, Wk, Wv);
    topk_kernel<<<B_ * H_, 256>>>();
    flash_local<<<dim3(S_ / 64, B_ * H_), 256, FL_SMEM>>>();
    flash_global<<<dim3(S_ / 64, B_ * H_), 256, FL_SMEM>>>(gam, bet);
    gate_kernel<<<(B_ * H_ * S_) / 4, 256>>>(Wg, bg);
    out_gemm<<<dim3(D_ / 64, (B_ * S_) / 64), 256>>>(Wo, bo, out);
}

// round 5
// speedup vs baseline: 1.9987x; 1.9987x over previous
#include <cuda_runtime.h>
#include <cuda_bf16.h>
#include <cstdint>

#define B_ 2
#define S_ 2048
#define D_ 1024
#define H_ 16
#define DH_ 64
#define NG_ 204
#define SCALE_ 0.125f

// ---------------- scratch (static device globals; no allocations) ----------------
__device__ float g_Q[B_ * H_ * DH_ * S_];    // [bh][d][s]  (transposed)
__device__ float g_K[B_ * H_ * DH_ * S_];    // [bh][d][s]  (transposed)
__device__ float g_V[B_ * H_ * S_ * DH_];    // [bh][s][d]
__device__ float g_Kg[B_ * H_ * DH_ * 256];  // [bh][d][g]  gathered, zero-padded
__device__ float g_Vg[B_ * H_ * 256 * DH_];  // [bh][g][d]  gathered, zero-padded
__device__ float g_local[B_ * H_ * S_ * DH_];
__device__ float g_glob[B_ * H_ * S_ * DH_];
__device__ float g_fused[B_ * S_ * D_];
__device__ int   g_topk[B_ * H_ * NG_];

// ================= mma.sync helpers =================
__device__ __forceinline__ void mma_bf16(float* c, const uint32_t* a, const uint32_t* b) {
    asm volatile(
        "mma.sync.aligned.m16n8k16.row.col.f32.bf16.bf16.f32 "
        "{%0,%1,%2,%3}, {%4,%5,%6,%7}, {%8,%9}, {%0,%1,%2,%3};"
        : "+f"(c[0]), "+f"(c[1]), "+f"(c[2]), "+f"(c[3])
        : "r"(a[0]), "r"(a[1]), "r"(a[2]), "r"(a[3]), "r"(b[0]), "r"(b[1]));
}
__device__ __forceinline__ void ldsm4(uint32_t* r, uint32_t addr) {
    asm volatile("ldmatrix.sync.aligned.m8n8.x4.shared.b16 {%0,%1,%2,%3}, [%4];"
                 : "=r"(r[0]), "=r"(r[1]), "=r"(r[2]), "=r"(r[3]) : "r"(addr));
}

// 2-term bf16 split of two fp32 values, packed bf16x2 (low half = first element)
__device__ __forceinline__ void split2(float x0, float x1, uint32_t& hi, uint32_t& lo) {
    __nv_bfloat16 h0 = __float2bfloat16(x0);
    __nv_bfloat16 h1 = __float2bfloat16(x1);
    float r0 = x0 - __bfloat162float(h0);
    float r1 = x1 - __bfloat162float(h1);
    __nv_bfloat162 Hh = __halves2bfloat162(h0, h1);
    __nv_bfloat162 Ll = __halves2bfloat162(__float2bfloat16(r0), __float2bfloat16(r1));
    hi = *reinterpret_cast<uint32_t*>(&Hh);
    lo = *reinterpret_cast<uint32_t*>(&Ll);
}

// ================= bf16-split mma GEMM: C[4096,1024] = A @ W =================
// CTA tile M=128, N=64, K-chunk=32. 8 warps (4 m x 2 n), warp tile 32x32.
// SMEM rows padded to 80B for conflict-free ldmatrix.
#define ROWB 80
#define A_H 0
#define A_L 10240
#define B_H 20480
#define B_L 25600
#define CSP 66
#define GEMM_SMEM 34816

__global__ void __launch_bounds__(256)
gemm_mma(const float* __restrict__ Ain,
         const float* __restrict__ W0, const float* __restrict__ W1,
         const float* __restrict__ W2,
         const float* __restrict__ bias, float* __restrict__ outp, int is_out) {
    extern __shared__ char smc[];
    const uint32_t smb = (uint32_t)__cvta_generic_to_shared(smc);
    float* Cs = (float*)smc;

    const int tid = threadIdx.x;
    const int wid = tid >> 5;
    const int lane = tid & 31;
    const int n0 = blockIdx.x * 64;
    const int m0 = blockIdx.y * 128;
    const int z = blockIdx.z;

    const float* A = is_out ? g_fused : Ain;
    const float* W = (z == 0) ? W0 : (z == 1 ? W1 : W2);

    const int warp_m0 = (wid & 3) * 32;
    const int warp_n0 = (wid >> 2) * 32;

    float acc[2][4][4] = {};

    // ldmatrix lane addressing (computed once)
    const int lrm = lane & 7;          // row within 8x8 matrix
    const int lmat = lane >> 3;        // which matrix 0..3
    // A: mats (r0-7,k0-7),(r8-15,k0-7),(r0-7,k8-15),(r8-15,k8-15)
    const int a_row = lrm + (lmat & 1) * 8;
    const int a_koff = (lmat >> 1) * 16;
    // B: mats (n0-7,k0-7),(n0-7,k8-15),(n8-15,k0-7),(n8-15,k8-15)
    const int b_row = lrm + (lmat >> 1) * 8;
    const int b_koff = (lmat & 1) * 16;

    for (int ch = 0; ch < 32; ch++) {
        const int K0 = ch * 32;
        __syncthreads();
        // ---- stage A[128][32] -> hi/lo bf16 ----
        {
            const float* Ab = A + (size_t)m0 * D_ + K0;
#pragma unroll
            for (int i = 0; i < 4; i++) {
                int e = tid + i * 256;
                int r = e >> 3, c4 = (e & 7) << 2;
                float4 v = *(const float4*)(Ab + (size_t)r * D_ + c4);
                uint32_t h0, l0, h1, l1;
                split2(v.x, v.y, h0, l0);
                split2(v.z, v.w, h1, l1);
                uint32_t off = (uint32_t)(r * ROWB + c4 * 2);
                *(uint2*)(smc + A_H + off) = make_uint2(h0, h1);
                *(uint2*)(smc + A_L + off) = make_uint2(l0, l1);
            }
        }
        // ---- stage B[n=64][k=32] = W[K0+k][n0+n] transposed -> hi/lo bf16 ----
        {
            int k = tid >> 3;            // 0..31
            int ng = (tid & 7) << 3;     // 0,8,..,56
            const float* Wr = W + (size_t)(K0 + k) * D_ + n0 + ng;
            float4 v0 = *(const float4*)(Wr);
            float4 v1 = *(const float4*)(Wr + 4);
            float vv[8] = {v0.x, v0.y, v0.z, v0.w, v1.x, v1.y, v1.z, v1.w};
#pragma unroll
            for (int j = 0; j < 8; j++) {
                float x = vv[j];
                __nv_bfloat16 h = __float2bfloat16(x);
                __nv_bfloat16 l = __float2bfloat16(x - __bfloat162float(h));
                uint32_t off = (uint32_t)((ng + j) * ROWB + k * 2);
                *(__nv_bfloat16*)(smc + B_H + off) = h;
                *(__nv_bfloat16*)(smc + B_L + off) = l;
            }
        }
        __syncthreads();

#pragma unroll
        for (int ks = 0; ks < 2; ks++) {
            uint32_t ah[2][4], al[2][4], bh[2][4], bl[2][4];
#pragma unroll
            for (int mt = 0; mt < 2; mt++) {
                uint32_t base = smb + (uint32_t)((warp_m0 + mt * 16 + a_row) * ROWB + ks * 32 + a_koff);
                ldsm4(ah[mt], base + A_H);
                ldsm4(al[mt], base + A_L);
            }
#pragma unroll
            for (int np = 0; np < 2; np++) {
                uint32_t base = smb + (uint32_t)((warp_n0 + np * 16 + b_row) * ROWB + ks * 32 + b_koff);
                ldsm4(bh[np], base + B_H);
                ldsm4(bl[np], base + B_L);
            }
#pragma unroll
            for (int mt = 0; mt < 2; mt++)
#pragma unroll
                for (int nt = 0; nt < 4; nt++) {
                    const uint32_t* Bh = &bh[nt >> 1][(nt & 1) * 2];
                    const uint32_t* Bl = &bl[nt >> 1][(nt & 1) * 2];
                    mma_bf16(acc[mt][nt], ah[mt], Bh);
                    mma_bf16(acc[mt][nt], ah[mt], Bl);
                    mma_bf16(acc[mt][nt], al[mt], Bh);
                }
        }
    }

    // ---- epilogue: fragments -> SMEM -> coalesced gmem ----
    __syncthreads();
#pragma unroll
    for (int mt = 0; mt < 2; mt++)
#pragma unroll
        for (int nt = 0; nt < 4; nt++) {
            int r = warp_m0 + mt * 16 + (lane >> 2);
            int c = warp_n0 + nt * 8 + (lane & 3) * 2;
            Cs[r * CSP + c]           = acc[mt][nt][0];
            Cs[r * CSP + c + 1]       = acc[mt][nt][1];
            Cs[(r + 8) * CSP + c]     = acc[mt][nt][2];
            Cs[(r + 8) * CSP + c + 1] = acc[mt][nt][3];
        }
    __syncthreads();

    const int bb = m0 >> 11;          // batch
    const int s0 = m0 & 2047;         // seq offset
    const int h = n0 >> 6;            // head
    if (is_out) {
        for (int e = tid; e < 8192; e += 256) {
            int sl = e >> 6, d = e & 63;
            outp[(size_t)(m0 + sl) * D_ + n0 + d] = Cs[sl * CSP + d] + bias[n0 + d];
        }
    } else if (z == 2) {
        float* dst = g_V + ((size_t)(bb * H_ + h) * S_ + s0) * 64;
        for (int e = tid; e < 8192; e += 256) {
            int sl = e >> 6, d = e & 63;
            dst[(size_t)sl * 64 + d] = Cs[sl * CSP + d];
        }
    } else {
        float* dst = (z == 0 ? g_Q : g_K) + ((size_t)(bb * H_ + h) * 64) * S_ + s0;
        for (int e = tid; e < 8192; e += 256) {
            int d = e >> 7, sl = e & 127;
            dst[(size_t)d * S_ + sl] = Cs[sl * CSP + d];
        }
    }
}

// ---------------- top-k by key norm (K is [bh][d][s]) ----------------
__global__ void topk_kernel() {
    __shared__ float nrm[S_];
    __shared__ int   ind[S_];
    const int bh = blockIdx.x;
    const float* Kp = g_K + (size_t)bh * 64 * S_;

    for (int s = threadIdx.x; s < S_; s += blockDim.x) {
        float sum = 0.f;
#pragma unroll 8
        for (int d = 0; d < 64; d++) { float v = Kp[(size_t)d * S_ + s]; sum += v * v; }
        nrm[s] = sum;
        ind[s] = s;
    }
    __syncthreads();
    for (int k = 2; k <= S_; k <<= 1) {
        for (int j = k >> 1; j > 0; j >>= 1) {
            for (int t = threadIdx.x; t < S_; t += blockDim.x) {
                int ixj = t ^ j;
                if (ixj > t) {
                    float a = nrm[t], b = nrm[ixj];
                    bool sw = ((t & k) == 0) ? (a > b) : (a < b);
                    if (sw) {
                        nrm[t] = b; nrm[ixj] = a;
                        int ti = ind[t]; ind[t] = ind[ixj]; ind[ixj] = ti;
                    }
                }
            }
            __syncthreads();
        }
    }
    for (int g = threadIdx.x; g < NG_; g += blockDim.x)
        g_topk[bh * NG_ + g] = ind[S_ - NG_ + g];
}

// ---------------- pack gathered global K/V (zero-padded to 256) ----------------
__global__ void gather_kernel() {
    __shared__ int ki[256];
    const int bh = blockIdx.x;
    const int tid = threadIdx.x;
    if (tid < 256) ki[tid] = (tid < NG_) ? g_topk[bh * NG_ + tid] : -1;
    __syncthreads();
    const float* Kp = g_K + (size_t)bh * 64 * S_;
    const float* Vp = g_V + (size_t)bh * S_ * 64;
    float* Kg = g_Kg + (size_t)bh * 64 * 256;
    float* Vg = g_Vg + (size_t)bh * 256 * 64;
    for (int e = tid; e < 64 * 256; e += blockDim.x) {
        int d = e >> 8, g = e & 255;
        int k = ki[g];
        Kg[d * 256 + g] = (k >= 0) ? Kp[(size_t)d * S_ + k] : 0.f;
    }
    for (int e = tid; e < 256 * 64; e += blockDim.x) {
        int g = e >> 6;
        int k = ki[g];
        Vg[e] = (k >= 0) ? Vp[(size_t)k * 64 + (e & 63)] : 0.f;
    }
}

// ---------------- flash attention (vectorized fp32) ----------------
#define FP 68
#define FL_SMEM (3 * 64 * FP * 4)

__device__ __forceinline__ float red_max16(float v) {
#pragma unroll
    for (int off = 8; off > 0; off >>= 1)
        v = fmaxf(v, __shfl_xor_sync(0xffffffffu, v, off, 16));
    return v;
}
__device__ __forceinline__ float red_sum16(float v) {
#pragma unroll
    for (int off = 8; off > 0; off >>= 1)
        v += __shfl_xor_sync(0xffffffffu, v, off, 16);
    return v;
}

__global__ void __launch_bounds__(256) flash_local() {
    extern __shared__ float sm[];
    float* Qt = sm;                 // [64 d][68]  (d-major)
    float* Kt = sm + 64 * FP;       // [64 d][68]; reused as Pt[c][qrow]
    float* Vs = sm + 2 * 64 * FP;   // [64 c][68]  (row-major [c][d])

    const int bh = blockIdx.y;
    const int q0 = blockIdx.x * 64;
    const int tid = threadIdx.x;
    const int tx = tid & 15, ty = tid >> 4;

    const float* Qp = g_Q + (size_t)bh * 64 * S_ + q0;
    const float* Kp = g_K + (size_t)bh * 64 * S_;
    const float* Vp = g_V + (size_t)bh * S_ * 64;

    for (int e4 = tid; e4 < 1024; e4 += 256) {
        int d = e4 >> 4, r4 = (e4 & 15) << 2;
        *(float4*)&Qt[d * FP + r4] = *(const float4*)(Qp + (size_t)d * S_ + r4);
    }

    float acc[4][4] = {};
    float mrow[4] = {-1e30f, -1e30f, -1e30f, -1e30f};
    float lrow[4] = {0.f, 0.f, 0.f, 0.f};

    for (int kt = 0; kt < S_ / 64; kt++) {
        __syncthreads();
        for (int e4 = tid; e4 < 1024; e4 += 256) {
            int d = e4 >> 4, r4 = (e4 & 15) << 2;
            *(float4*)&Kt[d * FP + r4] = *(const float4*)(Kp + (size_t)d * S_ + kt * 64 + r4);
            *(float4*)&Vs[d * FP + r4] = *(const float4*)(Vp + (size_t)(kt * 64 + d) * 64 + r4);
        }
        __syncthreads();

        float s[4][4] = {};
#pragma unroll 8
        for (int d = 0; d < 64; d++) {
            float4 a = *(const float4*)&Qt[d * FP + (ty << 2)];
            float4 b = *(const float4*)&Kt[d * FP + (tx << 2)];
            float av[4] = {a.x, a.y, a.z, a.w};
            float bv[4] = {b.x, b.y, b.z, b.w};
#pragma unroll
            for (int i = 0; i < 4; i++)
#pragma unroll
                for (int j = 0; j < 4; j++) s[i][j] += av[i] * bv[j];
        }

#pragma unroll
        for (int i = 0; i < 4; i++) {
            float mx = -1e30f;
#pragma unroll
            for (int j = 0; j < 4; j++) { s[i][j] *= SCALE_; mx = fmaxf(mx, s[i][j]); }
            mx = red_max16(mx);
            float mnew = fmaxf(mrow[i], mx);
            float corr = __expf(mrow[i] - mnew);
            mrow[i] = mnew;
            float ls = 0.f;
#pragma unroll
            for (int j = 0; j < 4; j++) { s[i][j] = __expf(s[i][j] - mnew); ls += s[i][j]; }
            ls = red_sum16(ls);
            lrow[i] = lrow[i] * corr + ls;
#pragma unroll
            for (int j = 0; j < 4; j++) acc[i][j] *= corr;
        }

        __syncthreads();
#pragma unroll
        for (int i = 0; i < 4; i++)
#pragma unroll
            for (int j = 0; j < 4; j++)
                Kt[(tx * 4 + j) * FP + ty * 4 + i] = s[i][j];   // Pt[c][qrow]
        __syncthreads();

#pragma unroll 8
        for (int c = 0; c < 64; c++) {
            float4 p = *(const float4*)&Kt[c * FP + (ty << 2)];
            float4 v = *(const float4*)&Vs[c * FP + (tx << 2)];
            float pv[4] = {p.x, p.y, p.z, p.w};
            float vv[4] = {v.x, v.y, v.z, v.w};
#pragma unroll
            for (int i = 0; i < 4; i++)
#pragma unroll
                for (int j = 0; j < 4; j++) acc[i][j] += pv[i] * vv[j];
        }
    }

    float* Op = g_local + ((size_t)bh * S_ + q0) * 64;
#pragma unroll
    for (int i = 0; i < 4; i++) {
        float inv = 1.f / lrow[i];
#pragma unroll
        for (int j = 0; j < 4; j++)
            Op[(ty * 4 + i) * 64 + tx * 4 + j] = acc[i][j] * inv;
    }
}

__global__ void __launch_bounds__(256) flash_global(const float* __restrict__ gamma,
                                                    const float* __restrict__ beta) {
    extern __shared__ float sm[];
    float* Qt = sm;
    float* Kt = sm + 64 * FP;
    float* Vs = sm + 2 * 64 * FP;

    const int bh = blockIdx.y;
    const int q0 = blockIdx.x * 64;
    const int tid = threadIdx.x;
    const int tx = tid & 15, ty = tid >> 4;

    const float* Qp = g_Q + (size_t)bh * 64 * S_ + q0;
    const float* Kg = g_Kg + (size_t)bh * 64 * 256;
    const float* Vg = g_Vg + (size_t)bh * 256 * 64;

    for (int e4 = tid; e4 < 1024; e4 += 256) {
        int d = e4 >> 4, r4 = (e4 & 15) << 2;
        *(float4*)&Qt[d * FP + r4] = *(const float4*)(Qp + (size_t)d * S_ + r4);
    }

    float acc[4][4] = {};
    float mrow[4] = {-1e30f, -1e30f, -1e30f, -1e30f};
    float lrow[4] = {0.f, 0.f, 0.f, 0.f};

    for (int kt = 0; kt < 4; kt++) {
        __syncthreads();
        for (int e4 = tid; e4 < 1024; e4 += 256) {
            int d = e4 >> 4, r4 = (e4 & 15) << 2;
            *(float4*)&Kt[d * FP + r4] = *(const float4*)(Kg + d * 256 + kt * 64 + r4);
            *(float4*)&Vs[d * FP + r4] = *(const float4*)(Vg + (kt * 64 + d) * 64 + r4);
        }
        __syncthreads();

        float s[4][4] = {};
#pragma unroll 8
        for (int d = 0; d < 64; d++) {
            float4 a = *(const float4*)&Qt[d * FP + (ty << 2)];
            float4 b = *(const float4*)&Kt[d * FP + (tx << 2)];
            float av[4] = {a.x, a.y, a.z, a.w};
            float bv[4] = {b.x, b.y, b.z, b.w};
#pragma unroll
            for (int i = 0; i < 4; i++)
#pragma unroll
                for (int j = 0; j < 4; j++) s[i][j] += av[i] * bv[j];
        }

#pragma unroll
        for (int i = 0; i < 4; i++) {
            float mx = -1e30f;
#pragma unroll
            for (int j = 0; j < 4; j++) {
                s[i][j] *= SCALE_;
                if (kt * 64 + tx * 4 + j >= NG_) s[i][j] = -1e30f;
                mx = fmaxf(mx, s[i][j]);
            }
            mx = red_max16(mx);
            float mnew = fmaxf(mrow[i], mx);
            float corr = __expf(mrow[i] - mnew);
            mrow[i] = mnew;
            float ls = 0.f;
#pragma unroll
            for (int j = 0; j < 4; j++) { s[i][j] = __expf(s[i][j] - mnew); ls += s[i][j]; }
            ls = red_sum16(ls);
            lrow[i] = lrow[i] * corr + ls;
#pragma unroll
            for (int j = 0; j < 4; j++) acc[i][j] *= corr;
        }

        __syncthreads();
#pragma unroll
        for (int i = 0; i < 4; i++)
#pragma unroll
            for (int j = 0; j < 4; j++)
                Kt[(tx * 4 + j) * FP + ty * 4 + i] = s[i][j];
        __syncthreads();

#pragma unroll 8
        for (int c = 0; c < 64; c++) {
            float4 p = *(const float4*)&Kt[c * FP + (ty << 2)];
            float4 v = *(const float4*)&Vs[c * FP + (tx << 2)];
            float pv[4] = {p.x, p.y, p.z, p.w};
            float vv[4] = {v.x, v.y, v.z, v.w};
#pragma unroll
            for (int i = 0; i < 4; i++)
#pragma unroll
                for (int j = 0; j < 4; j++) acc[i][j] += pv[i] * vv[j];
        }
    }

    // epilogue: /l, per-row LayerNorm over DH=64
    float* Op = g_glob + ((size_t)bh * S_ + q0) * 64;
#pragma unroll
    for (int i = 0; i < 4; i++) {
        float v[4];
        float linv = 1.f / lrow[i];
#pragma unroll
        for (int j = 0; j < 4; j++) v[j] = acc[i][j] * linv;
        float mu = v[0] + v[1] + v[2] + v[3];
        mu = red_sum16(mu) * (1.f / 64.f);
        float var = 0.f;
#pragma unroll
        for (int j = 0; j < 4; j++) { float t = v[j] - mu; var += t * t; }
        var = red_sum16(var) * (1.f / 64.f);
        float inv = rsqrtf(var + 1e-5f);
#pragma unroll
        for (int j = 0; j < 4; j++) {
            int c = tx * 4 + j;
            Op[(ty * 4 + i) * 64 + c] = (v[j] - mu) * inv * gamma[c] + beta[c];
        }
    }
}

// ---------------- gate: sigmoid([local, global] @ Wg + bg), fuse, repack ----------------
__global__ void gate_kernel(const float* __restrict__ Wg,
                            const float* __restrict__ bg) {
    __shared__ float Wgs[128 * 64];
    __shared__ float sloc[4][64];
    __shared__ float sglob[4][64];

    const int tid = threadIdx.x;
    for (int i = tid; i < 128 * 64; i += 256) Wgs[i] = Wg[i];

    const int r0 = blockIdx.x * 4;
    const int rs = tid >> 6;
    const int j  = tid & 63;
    const int r  = r0 + rs;

    sloc[rs][j]  = g_local[(size_t)r * 64 + j];
    sglob[rs][j] = g_glob[(size_t)r * 64 + j];
    __syncthreads();

    float acc = bg[j];
#pragma unroll 8
    for (int k = 0; k < 64; k++)
        acc += sloc[rs][k] * Wgs[k * 64 + j] + sglob[rs][k] * Wgs[(64 + k) * 64 + j];

    float g = 1.f / (1.f + __expf(-acc));
    float fused = g * sloc[rs][j] + (1.f - g) * sglob[rs][j];

    int bb = r / (H_ * S_);
    int h  = (r / S_) % H_;
    int ss = r % S_;
    g_fused[((size_t)bb * S_ + ss) * D_ + h * DH_ + j] = fused;
}

// ---------------- launch ----------------
extern "C" void kernel_launch(void* const* d_in, const int* in_sizes, int n_in,
                              void* d_out, int out_size) {
    (void)in_sizes; (void)n_in; (void)out_size;
    const float* x   = (const float*)d_in[0];
    const float* Wq  = (const float*)d_in[1];
    const float* Wk  = (const float*)d_in[2];
    const float* Wv  = (const float*)d_in[3];
    const float* Wo  = (const float*)d_in[4];
    const float* bo  = (const float*)d_in[5];
    const float* gam = (const float*)d_in[6];
    const float* bet = (const float*)d_in[7];
    const float* Wg  = (const float*)d_in[8];
    const float* bg  = (const float*)d_in[9];
    float* out = (float*)d_out;

    cudaFuncSetAttribute(gemm_mma, cudaFuncAttributeMaxDynamicSharedMemorySize, GEMM_SMEM);
    cudaFuncSetAttribute(flash_local,  cudaFuncAttributeMaxDynamicSharedMemorySize, FL_SMEM);
    cudaFuncSetAttribute(flash_global, cudaFuncAttributeMaxDynamicSharedMemorySize, FL_SMEM);

    gemm_mma<<<dim3(16, 32, 3), 256, GEMM_SMEM>>>(x, Wq, Wk, Wv, nullptr, nullptr, 0);
    topk_kernel<<<B_ * H_, 256>>>();
    gather_kernel<<<B_ * H_, 256>>>();
    flash_local<<<dim3(S_ / 64, B_ * H_), 256, FL_SMEM>>>();
    flash_global<<<dim3(S_ / 64, B_ * H_), 256, FL_SMEM>>>(gam, bet);
    gate_kernel<<<(B_ * H_ * S_) / 4, 256>>>(Wg, bg);
    gemm_mma<<<dim3(16, 32, 1), 256, GEMM_SMEM>>>(nullptr, Wo, Wo, Wo, bo, out, 1);
}

// round 6
// speedup vs baseline: 3.0895x; 1.5457x over previous
#include <cuda_runtime.h>
#include <cuda_bf16.h>
#include <cstdint>

#define B_ 2
#define S_ 2048
#define D_ 1024
#define H_ 16
#define DH_ 64
#define NG_ 204
#define SCALE_ 0.125f

// ---------------- scratch (static device globals; no allocations) ----------------
__device__ __nv_bfloat16 g_Qh[B_ * H_ * S_ * DH_];  // [bh][s][d], pre-scaled by SCALE_
__device__ __nv_bfloat16 g_Ql[B_ * H_ * S_ * DH_];
__device__ __nv_bfloat16 g_Kh[B_ * H_ * S_ * DH_];
__device__ __nv_bfloat16 g_Kl[B_ * H_ * S_ * DH_];
__device__ __nv_bfloat16 g_Vh[B_ * H_ * S_ * DH_];
__device__ __nv_bfloat16 g_Vl[B_ * H_ * S_ * DH_];
__device__ __nv_bfloat16 g_Kgh[B_ * H_ * 256 * DH_];  // gathered, zero-padded
__device__ __nv_bfloat16 g_Kgl[B_ * H_ * 256 * DH_];
__device__ __nv_bfloat16 g_Vgh[B_ * H_ * 256 * DH_];
__device__ __nv_bfloat16 g_Vgl[B_ * H_ * 256 * DH_];
__device__ float g_local[B_ * H_ * S_ * DH_];
__device__ float g_glob[B_ * H_ * S_ * DH_];
__device__ float g_fused[B_ * S_ * D_];
__device__ int   g_topk[B_ * H_ * NG_];

// ================= mma.sync helpers =================
__device__ __forceinline__ void mma_bf16(float* c, const uint32_t* a, const uint32_t* b) {
    asm volatile(
        "mma.sync.aligned.m16n8k16.row.col.f32.bf16.bf16.f32 "
        "{%0,%1,%2,%3}, {%4,%5,%6,%7}, {%8,%9}, {%0,%1,%2,%3};"
        : "+f"(c[0]), "+f"(c[1]), "+f"(c[2]), "+f"(c[3])
        : "r"(a[0]), "r"(a[1]), "r"(a[2]), "r"(a[3]), "r"(b[0]), "r"(b[1]));
}
__device__ __forceinline__ void ldsm4(uint32_t* r, uint32_t addr) {
    asm volatile("ldmatrix.sync.aligned.m8n8.x4.shared.b16 {%0,%1,%2,%3}, [%4];"
                 : "=r"(r[0]), "=r"(r[1]), "=r"(r[2]), "=r"(r[3]) : "r"(addr));
}
__device__ __forceinline__ void ldsm4t(uint32_t* r, uint32_t addr) {
    asm volatile("ldmatrix.sync.aligned.m8n8.x4.trans.shared.b16 {%0,%1,%2,%3}, [%4];"
                 : "=r"(r[0]), "=r"(r[1]), "=r"(r[2]), "=r"(r[3]) : "r"(addr));
}
__device__ __forceinline__ void cp16(uint32_t dst, const void* src) {
    asm volatile("cp.async.cg.shared.global [%0], [%1], 16;" :: "r"(dst), "l"(src));
}
__device__ __forceinline__ void cp_commit() { asm volatile("cp.async.commit_group;"); }
__device__ __forceinline__ void cp_wait0()  { asm volatile("cp.async.wait_group 0;"); }

// 2-term bf16 split of two fp32 values -> packed bf16x2 hi / lo (first elem low)
__device__ __forceinline__ void split2(float x0, float x1, uint32_t& hi, uint32_t& lo) {
    __nv_bfloat16 h0 = __float2bfloat16(x0);
    __nv_bfloat16 h1 = __float2bfloat16(x1);
    float r0 = x0 - __bfloat162float(h0);
    float r1 = x1 - __bfloat162float(h1);
    __nv_bfloat162 Hh = __halves2bfloat162(h0, h1);
    __nv_bfloat162 Ll = __halves2bfloat162(__float2bfloat16(r0), __float2bfloat16(r1));
    hi = *reinterpret_cast<uint32_t*>(&Hh);
    lo = *reinterpret_cast<uint32_t*>(&Ll);
}

// ================= bf16-split mma GEMM: C[4096,1024] = A @ W =================
#define ROWB 80
#define A_H 0
#define A_L 10240
#define B_H 20480
#define B_L 25600
#define CSP 66
#define GEMM_SMEM 34816

__global__ void __launch_bounds__(256)
gemm_mma(const float* __restrict__ Ain,
         const float* __restrict__ W0, const float* __restrict__ W1,
         const float* __restrict__ W2,
         const float* __restrict__ bias, float* __restrict__ outp, int is_out) {
    extern __shared__ char smc[];
    const uint32_t smb = (uint32_t)__cvta_generic_to_shared(smc);
    float* Cs = (float*)smc;

    const int tid = threadIdx.x;
    const int wid = tid >> 5;
    const int lane = tid & 31;
    const int n0 = blockIdx.x * 64;
    const int m0 = blockIdx.y * 128;
    const int z = blockIdx.z;

    const float* A = is_out ? g_fused : Ain;
    const float* W = (z == 0) ? W0 : (z == 1 ? W1 : W2);

    const int warp_m0 = (wid & 3) * 32;
    const int warp_n0 = (wid >> 2) * 32;

    float acc[2][4][4] = {};

    const int lrm = lane & 7;
    const int lmat = lane >> 3;
    const int a_row = lrm + (lmat & 1) * 8;
    const int a_koff = (lmat >> 1) * 16;
    const int b_row = lrm + (lmat >> 1) * 8;
    const int b_koff = (lmat & 1) * 16;

    for (int ch = 0; ch < 32; ch++) {
        const int K0 = ch * 32;
        __syncthreads();
        {
            const float* Ab = A + (size_t)m0 * D_ + K0;
#pragma unroll
            for (int i = 0; i < 4; i++) {
                int e = tid + i * 256;
                int r = e >> 3, c4 = (e & 7) << 2;
                float4 v = *(const float4*)(Ab + (size_t)r * D_ + c4);
                uint32_t h0, l0, h1, l1;
                split2(v.x, v.y, h0, l0);
                split2(v.z, v.w, h1, l1);
                uint32_t off = (uint32_t)(r * ROWB + c4 * 2);
                *(uint2*)(smc + A_H + off) = make_uint2(h0, h1);
                *(uint2*)(smc + A_L + off) = make_uint2(l0, l1);
            }
        }
        {
            int k = tid >> 3;
            int ng = (tid & 7) << 3;
            const float* Wr = W + (size_t)(K0 + k) * D_ + n0 + ng;
            float4 v0 = *(const float4*)(Wr);
            float4 v1 = *(const float4*)(Wr + 4);
            float vv[8] = {v0.x, v0.y, v0.z, v0.w, v1.x, v1.y, v1.z, v1.w};
#pragma unroll
            for (int j = 0; j < 8; j++) {
                float x = vv[j];
                __nv_bfloat16 h = __float2bfloat16(x);
                __nv_bfloat16 l = __float2bfloat16(x - __bfloat162float(h));
                uint32_t off = (uint32_t)((ng + j) * ROWB + k * 2);
                *(__nv_bfloat16*)(smc + B_H + off) = h;
                *(__nv_bfloat16*)(smc + B_L + off) = l;
            }
        }
        __syncthreads();

#pragma unroll
        for (int ks = 0; ks < 2; ks++) {
            uint32_t ah[2][4], al[2][4], bh[2][4], bl[2][4];
#pragma unroll
            for (int mt = 0; mt < 2; mt++) {
                uint32_t base = smb + (uint32_t)((warp_m0 + mt * 16 + a_row) * ROWB + ks * 32 + a_koff);
                ldsm4(ah[mt], base + A_H);
                ldsm4(al[mt], base + A_L);
            }
#pragma unroll
            for (int np = 0; np < 2; np++) {
                uint32_t base = smb + (uint32_t)((warp_n0 + np * 16 + b_row) * ROWB + ks * 32 + b_koff);
                ldsm4(bh[np], base + B_H);
                ldsm4(bl[np], base + B_L);
            }
#pragma unroll
            for (int mt = 0; mt < 2; mt++)
#pragma unroll
                for (int nt = 0; nt < 4; nt++) {
                    const uint32_t* Bh = &bh[nt >> 1][(nt & 1) * 2];
                    const uint32_t* Bl = &bl[nt >> 1][(nt & 1) * 2];
                    mma_bf16(acc[mt][nt], ah[mt], Bh);
                    mma_bf16(acc[mt][nt], ah[mt], Bl);
                    mma_bf16(acc[mt][nt], al[mt], Bh);
                }
        }
    }

    __syncthreads();
#pragma unroll
    for (int mt = 0; mt < 2; mt++)
#pragma unroll
        for (int nt = 0; nt < 4; nt++) {
            int r = warp_m0 + mt * 16 + (lane >> 2);
            int c = warp_n0 + nt * 8 + (lane & 3) * 2;
            Cs[r * CSP + c]           = acc[mt][nt][0];
            Cs[r * CSP + c + 1]       = acc[mt][nt][1];
            Cs[(r + 8) * CSP + c]     = acc[mt][nt][2];
            Cs[(r + 8) * CSP + c + 1] = acc[mt][nt][3];
        }
    __syncthreads();

    const int bb = m0 >> 11;
    const int s0 = m0 & 2047;
    const int h = n0 >> 6;
    if (is_out) {
        for (int e = tid; e < 8192; e += 256) {
            int sl = e >> 6, d = e & 63;
            outp[(size_t)(m0 + sl) * D_ + n0 + d] = Cs[sl * CSP + d] + bias[n0 + d];
        }
    } else {
        // write bf16 hi/lo pairs [bh][s][d]; Q pre-scaled by SCALE_
        __nv_bfloat16 *dh, *dl;
        if (z == 0)      { dh = g_Qh; dl = g_Ql; }
        else if (z == 1) { dh = g_Kh; dl = g_Kl; }
        else             { dh = g_Vh; dl = g_Vl; }
        const float sc = (z == 0) ? SCALE_ : 1.f;
        size_t base = ((size_t)(bb * H_ + h) * S_ + s0) * 64;
        for (int e = tid; e < 8192; e += 256) {
            int sl = e >> 6, d = e & 63;
            float x = Cs[sl * CSP + d] * sc;
            __nv_bfloat16 hv = __float2bfloat16(x);
            __nv_bfloat16 lv = __float2bfloat16(x - __bfloat162float(hv));
            dh[base + (size_t)sl * 64 + d] = hv;
            dl[base + (size_t)sl * 64 + d] = lv;
        }
    }
}

// ---------------- top-k by key norm (Kh/Kl are [bh][s][64]) ----------------
__global__ void topk_kernel() {
    __shared__ float nrm[S_];
    __shared__ int   ind[S_];
    const int bh = blockIdx.x;

    for (int s = threadIdx.x; s < S_; s += blockDim.x) {
        const __nv_bfloat162* kh = (const __nv_bfloat162*)(g_Kh + ((size_t)bh * S_ + s) * 64);
        const __nv_bfloat162* kl = (const __nv_bfloat162*)(g_Kl + ((size_t)bh * S_ + s) * 64);
        float sum = 0.f;
#pragma unroll 8
        for (int d = 0; d < 32; d++) {
            float2 h2 = __bfloat1622float2(kh[d]);
            float2 l2 = __bfloat1622float2(kl[d]);
            float v0 = h2.x + l2.x, v1 = h2.y + l2.y;
            sum += v0 * v0 + v1 * v1;
        }
        nrm[s] = sum;
        ind[s] = s;
    }
    __syncthreads();
    for (int k = 2; k <= S_; k <<= 1) {
        for (int j = k >> 1; j > 0; j >>= 1) {
            for (int t = threadIdx.x; t < S_; t += blockDim.x) {
                int ixj = t ^ j;
                if (ixj > t) {
                    float a = nrm[t], b = nrm[ixj];
                    bool sw = ((t & k) == 0) ? (a > b) : (a < b);
                    if (sw) {
                        nrm[t] = b; nrm[ixj] = a;
                        int ti = ind[t]; ind[t] = ind[ixj]; ind[ixj] = ti;
                    }
                }
            }
            __syncthreads();
        }
    }
    for (int g = threadIdx.x; g < NG_; g += blockDim.x)
        g_topk[bh * NG_ + g] = ind[S_ - NG_ + g];
}

// ---------------- pack gathered global K/V bf16 (zero-padded to 256 rows) ----------------
__global__ void gather_kernel() {
    __shared__ int ki[256];
    const int bh = blockIdx.x;
    const int tid = threadIdx.x;
    if (tid < 256) ki[tid] = (tid < NG_) ? g_topk[bh * NG_ + tid] : -1;
    __syncthreads();
    const size_t sb = (size_t)bh * S_ * 64;
    const size_t gb = (size_t)bh * 256 * 64;
    const uint4 zero = make_uint4(0, 0, 0, 0);
    for (int e = tid; e < 2048; e += blockDim.x) {   // 256 rows x 8 chunks of 16B
        int g = e >> 3, c = e & 7;
        int k = ki[g];
        size_t so = sb + (size_t)k * 64 + c * 8;
        size_t go = gb + (size_t)g * 64 + c * 8;
        *(uint4*)(g_Kgh + go) = (k >= 0) ? *(const uint4*)(g_Kh + so) : zero;
        *(uint4*)(g_Kgl + go) = (k >= 0) ? *(const uint4*)(g_Kl + so) : zero;
        *(uint4*)(g_Vgh + go) = (k >= 0) ? *(const uint4*)(g_Vh + so) : zero;
        *(uint4*)(g_Vgl + go) = (k >= 0) ? *(const uint4*)(g_Vl + so) : zero;
    }
}

// ================= flash attention via mma.sync (bf16 split) =================
// CTA: 128 q-rows, 8 warps (16 rows each). Key tiles of 64, double-buffered cp.async.
#define ROWQ 144
#define QH_OFF 0
#define QL_OFF 18432
#define KV0 36864
#define KVSZ 36864
#define KH_O 0
#define KL_O 9216
#define VH_O 18432
#define VL_O 27648
#define FLM_SMEM 110592

__global__ void __launch_bounds__(256) flash_mma(
    const __nv_bfloat16* __restrict__ Kh, const __nv_bfloat16* __restrict__ Kl,
    const __nv_bfloat16* __restrict__ Vh, const __nv_bfloat16* __restrict__ Vl,
    size_t kv_stride, int n_keys, int n_tiles,
    float* __restrict__ outp,
    const float* __restrict__ gamma, const float* __restrict__ beta, int do_ln) {
    extern __shared__ char smc[];
    const uint32_t smb = (uint32_t)__cvta_generic_to_shared(smc);
    const int tid = threadIdx.x;
    const int wid = tid >> 5;
    const int lane = tid & 31;
    const int bh = blockIdx.y;
    const int q0 = blockIdx.x * 128;

    const __nv_bfloat16* Qh = g_Qh + ((size_t)bh * S_ + q0) * 64;
    const __nv_bfloat16* Ql = g_Ql + ((size_t)bh * S_ + q0) * 64;
    Kh += (size_t)bh * kv_stride;
    Kl += (size_t)bh * kv_stride;
    Vh += (size_t)bh * kv_stride;
    Vl += (size_t)bh * kv_stride;
    outp += ((size_t)bh * S_ + q0) * 64;

    // prefetch key tile 0 (async) before staging Q
    const __nv_bfloat16* srcs[4] = {Kh, Kl, Vh, Vl};
    auto stage_tile = [&](int t, int bsel) {
        uint32_t dstb = smb + KV0 + bsel * KVSZ;
#pragma unroll
        for (int i = 0; i < 8; i++) {
            int e = tid + i * 256;
            int arr = e >> 9, r = (e >> 3) & 63, c = e & 7;
            cp16(dstb + arr * 9216 + r * ROWQ + c * 16,
                 srcs[arr] + (size_t)(t * 64 + r) * 64 + c * 8);
        }
        cp_commit();
    };
    stage_tile(0, 0);

    // stage Q (128 rows x 128B, hi/lo)
    for (int e = tid; e < 1024; e += 256) {
        int r = e >> 3, c = e & 7;
        *(uint4*)(smc + QH_OFF + r * ROWQ + c * 16) = *(const uint4*)(Qh + (size_t)r * 64 + c * 8);
        *(uint4*)(smc + QL_OFF + r * ROWQ + c * 16) = *(const uint4*)(Ql + (size_t)r * 64 + c * 8);
    }
    __syncthreads();

    const int lrm = lane & 7;
    const int lmat = lane >> 3;
    const int a_row = lrm + (lmat & 1) * 8;
    const int a_koff = (lmat >> 1) * 16;      // bytes
    const int b_row = lrm + (lmat >> 1) * 8;
    const int b_koff = (lmat & 1) * 16;       // bytes
    const int t_row = lrm + (lmat & 1) * 8;   // trans: row within key block
    const int t_col = (lmat >> 1) * 8;        // trans: d offset (elements)
    const int wm = wid * 16;

    // Q fragments (held all kernel)
    uint32_t aqh[4][4], aql[4][4];
#pragma unroll
    for (int ks = 0; ks < 4; ks++) {
        uint32_t ad = smb + QH_OFF + (uint32_t)((wm + a_row) * ROWQ + ks * 32 + a_koff);
        ldsm4(aqh[ks], ad);
        ldsm4(aql[ks], ad + (QL_OFF - QH_OFF));
    }

    float o[8][4] = {};
    float m0 = -1e30f, m1 = -1e30f, l0 = 0.f, l1 = 0.f;

    for (int t = 0; t < n_tiles; t++) {
        cp_wait0();
        __syncthreads();
        if (t + 1 < n_tiles) stage_tile(t + 1, (t + 1) & 1);
        const uint32_t bb = smb + KV0 + (uint32_t)(t & 1) * KVSZ;

        // ---- QK^T (3 split MMAs) ----
        float sc[8][4] = {};
#pragma unroll
        for (int ks = 0; ks < 4; ks++) {
            uint32_t kbh[4][4], kbl[4][4];
#pragma unroll
            for (int np = 0; np < 4; np++) {
                uint32_t ad = bb + KH_O + (uint32_t)((np * 16 + b_row) * ROWQ + ks * 32 + b_koff);
                ldsm4(kbh[np], ad);
                ldsm4(kbl[np], ad + (KL_O - KH_O));
            }
#pragma unroll
            for (int np = 0; np < 4; np++)
#pragma unroll
                for (int hf = 0; hf < 2; hf++) {
                    int j = np * 2 + hf;
                    mma_bf16(sc[j], aqh[ks], &kbh[np][hf * 2]);
                    mma_bf16(sc[j], aqh[ks], &kbl[np][hf * 2]);
                    mma_bf16(sc[j], aql[ks], &kbh[np][hf * 2]);
                }
        }

        // ---- mask tail ----
        if ((t + 1) * 64 > n_keys) {
            int cb = t * 64 + (lane & 3) * 2;
#pragma unroll
            for (int j = 0; j < 8; j++)
#pragma unroll
                for (int ii = 0; ii < 2; ii++) {
                    if (cb + j * 8 + ii >= n_keys) { sc[j][ii] = -1e30f; sc[j][2 + ii] = -1e30f; }
                }
        }

        // ---- online softmax on fragments ----
        float mx0 = -1e30f, mx1 = -1e30f;
#pragma unroll
        for (int j = 0; j < 8; j++) {
            mx0 = fmaxf(mx0, fmaxf(sc[j][0], sc[j][1]));
            mx1 = fmaxf(mx1, fmaxf(sc[j][2], sc[j][3]));
        }
        mx0 = fmaxf(mx0, __shfl_xor_sync(0xffffffffu, mx0, 1));
        mx0 = fmaxf(mx0, __shfl_xor_sync(0xffffffffu, mx0, 2));
        mx1 = fmaxf(mx1, __shfl_xor_sync(0xffffffffu, mx1, 1));
        mx1 = fmaxf(mx1, __shfl_xor_sync(0xffffffffu, mx1, 2));
        float mn0 = fmaxf(m0, mx0), mn1 = fmaxf(m1, mx1);
        float c0 = __expf(m0 - mn0), c1 = __expf(m1 - mn1);
        m0 = mn0; m1 = mn1;
        float s0 = 0.f, s1 = 0.f;
#pragma unroll
        for (int j = 0; j < 8; j++) {
            sc[j][0] = __expf(sc[j][0] - mn0); s0 += sc[j][0];
            sc[j][1] = __expf(sc[j][1] - mn0); s0 += sc[j][1];
            sc[j][2] = __expf(sc[j][2] - mn1); s1 += sc[j][2];
            sc[j][3] = __expf(sc[j][3] - mn1); s1 += sc[j][3];
        }
        s0 += __shfl_xor_sync(0xffffffffu, s0, 1);
        s0 += __shfl_xor_sync(0xffffffffu, s0, 2);
        s1 += __shfl_xor_sync(0xffffffffu, s1, 1);
        s1 += __shfl_xor_sync(0xffffffffu, s1, 2);
        l0 = l0 * c0 + s0;
        l1 = l1 * c1 + s1;
#pragma unroll
        for (int j = 0; j < 8; j++) {
            o[j][0] *= c0; o[j][1] *= c0; o[j][2] *= c1; o[j][3] *= c1;
        }

        // ---- P @ V (P from score frags, split; V via ldmatrix.trans) ----
#pragma unroll
        for (int ks = 0; ks < 4; ks++) {
            uint32_t pah[4], pal[4];
            split2(sc[2 * ks][0],     sc[2 * ks][1],     pah[0], pal[0]);
            split2(sc[2 * ks][2],     sc[2 * ks][3],     pah[1], pal[1]);
            split2(sc[2 * ks + 1][0], sc[2 * ks + 1][1], pah[2], pal[2]);
            split2(sc[2 * ks + 1][2], sc[2 * ks + 1][3], pah[3], pal[3]);
#pragma unroll
            for (int dp = 0; dp < 4; dp++) {
                uint32_t vbh[4], vbl[4];
                uint32_t ad = bb + VH_O + (uint32_t)((ks * 16 + t_row) * ROWQ + (dp * 16 + t_col) * 2);
                ldsm4t(vbh, ad);
                ldsm4t(vbl, ad + (VL_O - VH_O));
                mma_bf16(o[dp * 2],     pah, &vbh[0]);
                mma_bf16(o[dp * 2],     pah, &vbl[0]);
                mma_bf16(o[dp * 2],     pal, &vbh[0]);
                mma_bf16(o[dp * 2 + 1], pah, &vbh[2]);
                mma_bf16(o[dp * 2 + 1], pah, &vbl[2]);
                mma_bf16(o[dp * 2 + 1], pal, &vbh[2]);
            }
        }
    }

    // ---- epilogue ----
    const float inv0 = 1.f / l0, inv1 = 1.f / l1;
    const int rq = wm + (lane >> 2);
    const int cb = (lane & 3) * 2;
    if (!do_ln) {
#pragma unroll
        for (int j = 0; j < 8; j++) {
            *(float2*)(outp + (size_t)rq * 64 + j * 8 + cb) =
                make_float2(o[j][0] * inv0, o[j][1] * inv0);
            *(float2*)(outp + (size_t)(rq + 8) * 64 + j * 8 + cb) =
                make_float2(o[j][2] * inv1, o[j][3] * inv1);
        }
    } else {
        float v0[8][2], v1[8][2];
        float sum0 = 0.f, sum1 = 0.f;
#pragma unroll
        for (int j = 0; j < 8; j++) {
            v0[j][0] = o[j][0] * inv0; v0[j][1] = o[j][1] * inv0;
            v1[j][0] = o[j][2] * inv1; v1[j][1] = o[j][3] * inv1;
            sum0 += v0[j][0] + v0[j][1];
            sum1 += v1[j][0] + v1[j][1];
        }
        sum0 += __shfl_xor_sync(0xffffffffu, sum0, 1);
        sum0 += __shfl_xor_sync(0xffffffffu, sum0, 2);
        sum1 += __shfl_xor_sync(0xffffffffu, sum1, 1);
        sum1 += __shfl_xor_sync(0xffffffffu, sum1, 2);
        float mu0 = sum0 * (1.f / 64.f), mu1 = sum1 * (1.f / 64.f);
        float var0 = 0.f, var1 = 0.f;
#pragma unroll
        for (int j = 0; j < 8; j++) {
            float a0 = v0[j][0] - mu0, a1 = v0[j][1] - mu0;
            float b0 = v1[j][0] - mu1, b1 = v1[j][1] - mu1;
            var0 += a0 * a0 + a1 * a1;
            var1 += b0 * b0 + b1 * b1;
        }
        var0 += __shfl_xor_sync(0xffffffffu, var0, 1);
        var0 += __shfl_xor_sync(0xffffffffu, var0, 2);
        var1 += __shfl_xor_sync(0xffffffffu, var1, 1);
        var1 += __shfl_xor_sync(0xffffffffu, var1, 2);
        float is0 = rsqrtf(var0 * (1.f / 64.f) + 1e-5f);
        float is1 = rsqrtf(var1 * (1.f / 64.f) + 1e-5f);
#pragma unroll
        for (int j = 0; j < 8; j++) {
            int col = j * 8 + cb;
            float g0 = gamma[col], g1 = gamma[col + 1];
            float be0 = beta[col], be1 = beta[col + 1];
            *(float2*)(outp + (size_t)rq * 64 + col) =
                make_float2((v0[j][0] - mu0) * is0 * g0 + be0,
                            (v0[j][1] - mu0) * is0 * g1 + be1);
            *(float2*)(outp + (size_t)(rq + 8) * 64 + col) =
                make_float2((v1[j][0] - mu1) * is1 * g0 + be0,
                            (v1[j][1] - mu1) * is1 * g1 + be1);
        }
    }
}

// ---------------- gate: sigmoid([local, global] @ Wg + bg), fuse, repack ----------------
__global__ void gate_kernel(const float* __restrict__ Wg,
                            const float* __restrict__ bg) {
    __shared__ float Wgs[128 * 64];
    __shared__ float sloc[4][64];
    __shared__ float sglob[4][64];

    const int tid = threadIdx.x;
    for (int i = tid; i < 128 * 64; i += 256) Wgs[i] = Wg[i];

    const int r0 = blockIdx.x * 4;
    const int rs = tid >> 6;
    const int j  = tid & 63;
    const int r  = r0 + rs;

    sloc[rs][j]  = g_local[(size_t)r * 64 + j];
    sglob[rs][j] = g_glob[(size_t)r * 64 + j];
    __syncthreads();

    float acc = bg[j];
#pragma unroll 8
    for (int k = 0; k < 64; k++)
        acc += sloc[rs][k] * Wgs[k * 64 + j] + sglob[rs][k] * Wgs[(64 + k) * 64 + j];

    float g = 1.f / (1.f + __expf(-acc));
    float fused = g * sloc[rs][j] + (1.f - g) * sglob[rs][j];

    int bb = r / (H_ * S_);
    int h  = (r / S_) % H_;
    int ss = r % S_;
    g_fused[((size_t)bb * S_ + ss) * D_ + h * DH_ + j] = fused;
}

// ---------------- launch ----------------
extern "C" void kernel_launch(void* const* d_in, const int* in_sizes, int n_in,
                              void* d_out, int out_size) {
    (void)in_sizes; (void)n_in; (void)out_size;
    const float* x   = (const float*)d_in[0];
    const float* Wq  = (const float*)d_in[1];
    const float* Wk  = (const float*)d_in[2];
    const float* Wv  = (const float*)d_in[3];
    const float* Wo  = (const float*)d_in[4];
    const float* bo  = (const float*)d_in[5];
    const float* gam = (const float*)d_in[6];
    const float* bet = (const float*)d_in[7];
    const float* Wg  = (const float*)d_in[8];
    const float* bg  = (const float*)d_in[9];
    float* out = (float*)d_out;

    cudaFuncSetAttribute(gemm_mma,  cudaFuncAttributeMaxDynamicSharedMemorySize, GEMM_SMEM);
    cudaFuncSetAttribute(flash_mma, cudaFuncAttributeMaxDynamicSharedMemorySize, FLM_SMEM);

    __nv_bfloat16 *kh, *kl, *vh, *vl, *kgh, *kgl, *vgh, *vgl;
    float *lo, *gl;
    cudaGetSymbolAddress((void**)&kh,  g_Kh);
    cudaGetSymbolAddress((void**)&kl,  g_Kl);
    cudaGetSymbolAddress((void**)&vh,  g_Vh);
    cudaGetSymbolAddress((void**)&vl,  g_Vl);
    cudaGetSymbolAddress((void**)&kgh, g_Kgh);
    cudaGetSymbolAddress((void**)&kgl, g_Kgl);
    cudaGetSymbolAddress((void**)&vgh, g_Vgh);
    cudaGetSymbolAddress((void**)&vgl, g_Vgl);
    cudaGetSymbolAddress((void**)&lo,  g_local);
    cudaGetSymbolAddress((void**)&gl,  g_glob);

    gemm_mma<<<dim3(16, 32, 3), 256, GEMM_SMEM>>>(x, Wq, Wk, Wv, nullptr, nullptr, 0);
    topk_kernel<<<B_ * H_, 256>>>();
    gather_kernel<<<B_ * H_, 256>>>();
    flash_mma<<<dim3(S_ / 128, B_ * H_), 256, FLM_SMEM>>>(
        kh, kl, vh, vl, (size_t)S_ * 64, S_, S_ / 64, lo, gam, bet, 0);
    flash_mma<<<dim3(S_ / 128, B_ * H_), 256, FLM_SMEM>>>(
        kgh, kgl, vgh, vgl, (size_t)256 * 64, NG_, 4, gl, gam, bet, 1);
    gate_kernel<<<(B_ * H_ * S_) / 4, 256>>>(Wg, bg);
    gemm_mma<<<dim3(16, 32, 1), 256, GEMM_SMEM>>>(nullptr, Wo, Wo, Wo, bo, out, 1);
}

// round 7
// speedup vs baseline: 4.1459x; 1.3420x over previous
#include <cuda_runtime.h>
#include <cuda_bf16.h>
#include <cstdint>

#define B_ 2
#define S_ 2048
#define D_ 1024
#define H_ 16
#define DH_ 64
#define NG_ 204
#define SCALE_ 0.125f

// ---------------- scratch (static device globals; no allocations) ----------------
__device__ __nv_bfloat16 g_Qh[B_ * H_ * S_ * DH_];  // [bh][s][d], pre-scaled by SCALE_
__device__ __nv_bfloat16 g_Ql[B_ * H_ * S_ * DH_];
__device__ __nv_bfloat16 g_Kh[B_ * H_ * S_ * DH_];
__device__ __nv_bfloat16 g_Kl[B_ * H_ * S_ * DH_];
__device__ __nv_bfloat16 g_Vh[B_ * H_ * S_ * DH_];
__device__ __nv_bfloat16 g_Vl[B_ * H_ * S_ * DH_];
__device__ __nv_bfloat16 g_Kgh[B_ * H_ * 256 * DH_];  // gathered, zero-padded
__device__ __nv_bfloat16 g_Kgl[B_ * H_ * 256 * DH_];
__device__ __nv_bfloat16 g_Vgh[B_ * H_ * 256 * DH_];
__device__ __nv_bfloat16 g_Vgl[B_ * H_ * 256 * DH_];
__device__ __nv_bfloat16 g_Xh[B_ * S_ * D_];         // split input x
__device__ __nv_bfloat16 g_Xl[B_ * S_ * D_];
__device__ __nv_bfloat16 g_Fh[B_ * S_ * D_];         // split fused (gate output)
__device__ __nv_bfloat16 g_Fl[B_ * S_ * D_];
__device__ __nv_bfloat16 g_Wth[4 * D_ * D_];         // W^T [z][n][k] split
__device__ __nv_bfloat16 g_Wtl[4 * D_ * D_];
__device__ float g_local[B_ * H_ * S_ * DH_];
__device__ float g_glob[B_ * H_ * S_ * DH_];
__device__ int   g_topk[B_ * H_ * NG_];

// ================= mma.sync helpers =================
__device__ __forceinline__ void mma_bf16(float* c, const uint32_t* a, const uint32_t* b) {
    asm volatile(
        "mma.sync.aligned.m16n8k16.row.col.f32.bf16.bf16.f32 "
        "{%0,%1,%2,%3}, {%4,%5,%6,%7}, {%8,%9}, {%0,%1,%2,%3};"
        : "+f"(c[0]), "+f"(c[1]), "+f"(c[2]), "+f"(c[3])
        : "r"(a[0]), "r"(a[1]), "r"(a[2]), "r"(a[3]), "r"(b[0]), "r"(b[1]));
}
__device__ __forceinline__ void ldsm4(uint32_t* r, uint32_t addr) {
    asm volatile("ldmatrix.sync.aligned.m8n8.x4.shared.b16 {%0,%1,%2,%3}, [%4];"
                 : "=r"(r[0]), "=r"(r[1]), "=r"(r[2]), "=r"(r[3]) : "r"(addr));
}
__device__ __forceinline__ void ldsm4t(uint32_t* r, uint32_t addr) {
    asm volatile("ldmatrix.sync.aligned.m8n8.x4.trans.shared.b16 {%0,%1,%2,%3}, [%4];"
                 : "=r"(r[0]), "=r"(r[1]), "=r"(r[2]), "=r"(r[3]) : "r"(addr));
}
__device__ __forceinline__ void cp16(uint32_t dst, const void* src) {
    asm volatile("cp.async.cg.shared.global [%0], [%1], 16;" :: "r"(dst), "l"(src));
}
__device__ __forceinline__ void cp_commit() { asm volatile("cp.async.commit_group;"); }
__device__ __forceinline__ void cp_wait0()  { asm volatile("cp.async.wait_group 0;"); }

// 2-term bf16 split of two fp32 values -> packed bf16x2 hi / lo
__device__ __forceinline__ void split2(float x0, float x1, uint32_t& hi, uint32_t& lo) {
    __nv_bfloat16 h0 = __float2bfloat16(x0);
    __nv_bfloat16 h1 = __float2bfloat16(x1);
    float r0 = x0 - __bfloat162float(h0);
    float r1 = x1 - __bfloat162float(h1);
    __nv_bfloat162 Hh = __halves2bfloat162(h0, h1);
    __nv_bfloat162 Ll = __halves2bfloat162(__float2bfloat16(r0), __float2bfloat16(r1));
    hi = *reinterpret_cast<uint32_t*>(&Hh);
    lo = *reinterpret_cast<uint32_t*>(&Ll);
}

// ================= pre-conversion kernels =================
__global__ void conv_x(const float* __restrict__ x) {
    int idx = blockIdx.x * 256 + threadIdx.x;       // float4 index
    float4 v = *(const float4*)(x + (size_t)idx * 4);
    uint32_t h0, l0, h1, l1;
    split2(v.x, v.y, h0, l0);
    split2(v.z, v.w, h1, l1);
    *(uint2*)(g_Xh + (size_t)idx * 4) = make_uint2(h0, h1);
    *(uint2*)(g_Xl + (size_t)idx * 4) = make_uint2(l0, l1);
}

// transpose + split W[k][n] -> Wt[z][n][k]
__global__ void conv_wt(const float* __restrict__ W0, const float* __restrict__ W1,
                        const float* __restrict__ W2, const float* __restrict__ W3) {
    __shared__ float t[32][33];
    const int z = blockIdx.z;
    const float* W = (z == 0) ? W0 : (z == 1) ? W1 : (z == 2) ? W2 : W3;
    const int n0 = blockIdx.x * 32, k0 = blockIdx.y * 32;
    const int tx = threadIdx.x, ty = threadIdx.y;
#pragma unroll
    for (int i = 0; i < 4; i++)
        t[ty + i * 8][tx] = W[(size_t)(k0 + ty + i * 8) * D_ + n0 + tx];
    __syncthreads();
    size_t ob = (size_t)z * D_ * D_;
#pragma unroll
    for (int i = 0; i < 4; i++) {
        float v = t[tx][ty + i * 8];
        __nv_bfloat16 h = __float2bfloat16(v);
        __nv_bfloat16 l = __float2bfloat16(v - __bfloat162float(h));
        size_t o = ob + (size_t)(n0 + ty + i * 8) * D_ + k0 + tx;
        g_Wth[o] = h;
        g_Wtl[o] = l;
    }
}

// ================= bf16-split mma GEMM (pre-split inputs, cp.async 2-stage) =================
// CTA tile M=128, N=64, K-chunk 64. 8 warps (4m x 2n), warp tile 32x32.
#define G2R 144
#define G2_AH 0
#define G2_AL 18432
#define G2_BH 36864
#define G2_BL 46080
#define G2_STG 55296
#define GEMM2_SMEM 110592
#define CSP 66

__global__ void __launch_bounds__(256, 2)
gemm_bf16(const __nv_bfloat16* __restrict__ Ah, const __nv_bfloat16* __restrict__ Al,
          const float* __restrict__ bias, float* __restrict__ outp, int is_out) {
    extern __shared__ char smc[];
    const uint32_t smb = (uint32_t)__cvta_generic_to_shared(smc);
    float* Cs = (float*)smc;

    const int tid = threadIdx.x;
    const int wid = tid >> 5;
    const int lane = tid & 31;
    const int n0 = blockIdx.x * 64;
    const int m0 = blockIdx.y * 128;
    const int z = blockIdx.z;
    const size_t woff = (size_t)(is_out ? 3 : z) * D_ * D_;

    const int warp_m0 = (wid & 3) * 32;
    const int warp_n0 = (wid >> 2) * 32;

    auto stage = [&](int ch) {
        uint32_t sb = smb + (uint32_t)(ch & 1) * G2_STG;
        const int K0 = ch * 64;
#pragma unroll
        for (int i = 0; i < 8; i++) {     // A: 2048 cp16 (hi+lo)
            int e = tid + i * 256;
            int half = e >> 10, r = (e >> 3) & 127, c = e & 7;
            const __nv_bfloat16* src = (half ? Al : Ah) + (size_t)(m0 + r) * D_ + K0 + c * 8;
            cp16(sb + (half ? G2_AL : G2_AH) + r * G2R + c * 16, src);
        }
#pragma unroll
        for (int i = 0; i < 4; i++) {     // B: 1024 cp16 (hi+lo)
            int e = tid + i * 256;
            int half = e >> 9, n = (e >> 3) & 63, c = e & 7;
            const __nv_bfloat16* src = (half ? g_Wtl : g_Wth) + woff +
                                       (size_t)(n0 + n) * D_ + K0 + c * 8;
            cp16(sb + (half ? G2_BL : G2_BH) + n * G2R + c * 16, src);
        }
        cp_commit();
    };

    float acc[2][4][4] = {};

    const int lrm = lane & 7;
    const int lmat = lane >> 3;
    const int a_row = lrm + (lmat & 1) * 8;
    const int a_koff = (lmat >> 1) * 16;
    const int b_row = lrm + (lmat >> 1) * 8;
    const int b_koff = (lmat & 1) * 16;

    stage(0);
    for (int ch = 0; ch < 16; ch++) {
        cp_wait0();
        __syncthreads();
        if (ch + 1 < 16) stage(ch + 1);
        const uint32_t sb = smb + (uint32_t)(ch & 1) * G2_STG;

#pragma unroll
        for (int ks = 0; ks < 4; ks++) {
            uint32_t ah[2][4], al[2][4], bh[2][4], bl[2][4];
#pragma unroll
            for (int mt = 0; mt < 2; mt++) {
                uint32_t ad = sb + G2_AH + (uint32_t)((warp_m0 + mt * 16 + a_row) * G2R + ks * 32 + a_koff);
                ldsm4(ah[mt], ad);
                ldsm4(al[mt], ad + (G2_AL - G2_AH));
            }
#pragma unroll
            for (int np = 0; np < 2; np++) {
                uint32_t ad = sb + G2_BH + (uint32_t)((warp_n0 + np * 16 + b_row) * G2R + ks * 32 + b_koff);
                ldsm4(bh[np], ad);
                ldsm4(bl[np], ad + (G2_BL - G2_BH));
            }
#pragma unroll
            for (int mt = 0; mt < 2; mt++)
#pragma unroll
                for (int nt = 0; nt < 4; nt++) {
                    const uint32_t* Bh = &bh[nt >> 1][(nt & 1) * 2];
                    const uint32_t* Bl = &bl[nt >> 1][(nt & 1) * 2];
                    mma_bf16(acc[mt][nt], ah[mt], Bh);
                    mma_bf16(acc[mt][nt], ah[mt], Bl);
                    mma_bf16(acc[mt][nt], al[mt], Bh);
                }
        }
        __syncthreads();
    }

    // ---- epilogue: fragments -> SMEM -> coalesced gmem ----
#pragma unroll
    for (int mt = 0; mt < 2; mt++)
#pragma unroll
        for (int nt = 0; nt < 4; nt++) {
            int r = warp_m0 + mt * 16 + (lane >> 2);
            int c = warp_n0 + nt * 8 + (lane & 3) * 2;
            Cs[r * CSP + c]           = acc[mt][nt][0];
            Cs[r * CSP + c + 1]       = acc[mt][nt][1];
            Cs[(r + 8) * CSP + c]     = acc[mt][nt][2];
            Cs[(r + 8) * CSP + c + 1] = acc[mt][nt][3];
        }
    __syncthreads();

    const int bb = m0 >> 11;
    const int s0 = m0 & 2047;
    const int h = n0 >> 6;
    if (is_out) {
        for (int e = tid; e < 8192; e += 256) {
            int sl = e >> 6, d = e & 63;
            outp[(size_t)(m0 + sl) * D_ + n0 + d] = Cs[sl * CSP + d] + bias[n0 + d];
        }
    } else {
        __nv_bfloat16 *dh, *dl;
        if (z == 0)      { dh = g_Qh; dl = g_Ql; }
        else if (z == 1) { dh = g_Kh; dl = g_Kl; }
        else             { dh = g_Vh; dl = g_Vl; }
        const float sc = (z == 0) ? SCALE_ : 1.f;
        size_t base = ((size_t)(bb * H_ + h) * S_ + s0) * 64;
        for (int e = tid; e < 8192; e += 256) {
            int sl = e >> 6, d = e & 63;
            float x = Cs[sl * CSP + d] * sc;
            __nv_bfloat16 hv = __float2bfloat16(x);
            __nv_bfloat16 lv = __float2bfloat16(x - __bfloat162float(hv));
            dh[base + (size_t)sl * 64 + d] = hv;
            dl[base + (size_t)sl * 64 + d] = lv;
        }
    }
}

// ---------------- top-k by key norm (Kh/Kl are [bh][s][64]) ----------------
__global__ void __launch_bounds__(1024) topk_kernel() {
    __shared__ float nrm[S_];
    __shared__ int   ind[S_];
    const int bh = blockIdx.x;

    for (int s = threadIdx.x; s < S_; s += blockDim.x) {
        const __nv_bfloat162* kh = (const __nv_bfloat162*)(g_Kh + ((size_t)bh * S_ + s) * 64);
        const __nv_bfloat162* kl = (const __nv_bfloat162*)(g_Kl + ((size_t)bh * S_ + s) * 64);
        float sum = 0.f;
#pragma unroll 8
        for (int d = 0; d < 32; d++) {
            float2 h2 = __bfloat1622float2(kh[d]);
            float2 l2 = __bfloat1622float2(kl[d]);
            float v0 = h2.x + l2.x, v1 = h2.y + l2.y;
            sum += v0 * v0 + v1 * v1;
        }
        nrm[s] = sum;
        ind[s] = s;
    }
    __syncthreads();
    for (int k = 2; k <= S_; k <<= 1) {
        for (int j = k >> 1; j > 0; j >>= 1) {
            for (int t = threadIdx.x; t < S_; t += blockDim.x) {
                int ixj = t ^ j;
                if (ixj > t) {
                    float a = nrm[t], b = nrm[ixj];
                    bool sw = ((t & k) == 0) ? (a > b) : (a < b);
                    if (sw) {
                        nrm[t] = b; nrm[ixj] = a;
                        int ti = ind[t]; ind[t] = ind[ixj]; ind[ixj] = ti;
                    }
                }
            }
            __syncthreads();
        }
    }
    for (int g = threadIdx.x; g < NG_; g += blockDim.x)
        g_topk[bh * NG_ + g] = ind[S_ - NG_ + g];
}

// ---------------- pack gathered global K/V bf16 (zero-padded to 256 rows) ----------------
__global__ void gather_kernel() {
    __shared__ int ki[256];
    const int bh = blockIdx.x;
    const int tid = threadIdx.x;
    if (tid < 256) ki[tid] = (tid < NG_) ? g_topk[bh * NG_ + tid] : -1;
    __syncthreads();
    const size_t sb = (size_t)bh * S_ * 64;
    const size_t gb = (size_t)bh * 256 * 64;
    const uint4 zero = make_uint4(0, 0, 0, 0);
    for (int e = tid; e < 2048; e += blockDim.x) {
        int g = e >> 3, c = e & 7;
        int k = ki[g];
        size_t so = sb + (size_t)k * 64 + c * 8;
        size_t go = gb + (size_t)g * 64 + c * 8;
        *(uint4*)(g_Kgh + go) = (k >= 0) ? *(const uint4*)(g_Kh + so) : zero;
        *(uint4*)(g_Kgl + go) = (k >= 0) ? *(const uint4*)(g_Kl + so) : zero;
        *(uint4*)(g_Vgh + go) = (k >= 0) ? *(const uint4*)(g_Vh + so) : zero;
        *(uint4*)(g_Vgl + go) = (k >= 0) ? *(const uint4*)(g_Vl + so) : zero;
    }
}

// ================= flash attention via mma.sync (bf16 split) =================
#define ROWQ 144
#define QH_OFF 0
#define QL_OFF 18432
#define KV0 36864
#define KVSZ 36864
#define KH_O 0
#define KL_O 9216
#define VH_O 18432
#define VL_O 27648
#define FLM_SMEM 110592

__global__ void __launch_bounds__(256, 2) flash_mma(
    const __nv_bfloat16* __restrict__ Kh, const __nv_bfloat16* __restrict__ Kl,
    const __nv_bfloat16* __restrict__ Vh, const __nv_bfloat16* __restrict__ Vl,
    size_t kv_stride, int n_keys, int n_tiles,
    float* __restrict__ outp,
    const float* __restrict__ gamma, const float* __restrict__ beta, int do_ln) {
    extern __shared__ char smc[];
    const uint32_t smb = (uint32_t)__cvta_generic_to_shared(smc);
    const int tid = threadIdx.x;
    const int wid = tid >> 5;
    const int lane = tid & 31;
    const int bh = blockIdx.y;
    const int q0 = blockIdx.x * 128;

    const __nv_bfloat16* Qh = g_Qh + ((size_t)bh * S_ + q0) * 64;
    const __nv_bfloat16* Ql = g_Ql + ((size_t)bh * S_ + q0) * 64;
    Kh += (size_t)bh * kv_stride;
    Kl += (size_t)bh * kv_stride;
    Vh += (size_t)bh * kv_stride;
    Vl += (size_t)bh * kv_stride;
    outp += ((size_t)bh * S_ + q0) * 64;

    const __nv_bfloat16* srcs[4] = {Kh, Kl, Vh, Vl};
    auto stage_tile = [&](int t, int bsel) {
        uint32_t dstb = smb + KV0 + bsel * KVSZ;
#pragma unroll
        for (int i = 0; i < 8; i++) {
            int e = tid + i * 256;
            int arr = e >> 9, r = (e >> 3) & 63, c = e & 7;
            cp16(dstb + arr * 9216 + r * ROWQ + c * 16,
                 srcs[arr] + (size_t)(t * 64 + r) * 64 + c * 8);
        }
        cp_commit();
    };
    stage_tile(0, 0);

    for (int e = tid; e < 1024; e += 256) {
        int r = e >> 3, c = e & 7;
        *(uint4*)(smc + QH_OFF + r * ROWQ + c * 16) = *(const uint4*)(Qh + (size_t)r * 64 + c * 8);
        *(uint4*)(smc + QL_OFF + r * ROWQ + c * 16) = *(const uint4*)(Ql + (size_t)r * 64 + c * 8);
    }
    __syncthreads();

    const int lrm = lane & 7;
    const int lmat = lane >> 3;
    const int a_row = lrm + (lmat & 1) * 8;
    const int a_koff = (lmat >> 1) * 16;
    const int b_row = lrm + (lmat >> 1) * 8;
    const int b_koff = (lmat & 1) * 16;
    const int t_row = lrm + (lmat & 1) * 8;
    const int t_col = (lmat >> 1) * 8;
    const int wm = wid * 16;

    float o[8][4] = {};
    float m0 = -1e30f, m1 = -1e30f, l0 = 0.f, l1 = 0.f;

    for (int t = 0; t < n_tiles; t++) {
        cp_wait0();
        __syncthreads();
        if (t + 1 < n_tiles) stage_tile(t + 1, (t + 1) & 1);
        const uint32_t bb = smb + KV0 + (uint32_t)(t & 1) * KVSZ;

        // ---- QK^T (3 split MMAs), Q frags reloaded per ks (saves 32 regs) ----
        float sc[8][4] = {};
#pragma unroll
        for (int ks = 0; ks < 4; ks++) {
            uint32_t aqh[4], aql[4];
            uint32_t qa = smb + QH_OFF + (uint32_t)((wm + a_row) * ROWQ + ks * 32 + a_koff);
            ldsm4(aqh, qa);
            ldsm4(aql, qa + (QL_OFF - QH_OFF));
            uint32_t kbh[4][4], kbl[4][4];
#pragma unroll
            for (int np = 0; np < 4; np++) {
                uint32_t ad = bb + KH_O + (uint32_t)((np * 16 + b_row) * ROWQ + ks * 32 + b_koff);
                ldsm4(kbh[np], ad);
                ldsm4(kbl[np], ad + (KL_O - KH_O));
            }
#pragma unroll
            for (int np = 0; np < 4; np++)
#pragma unroll
                for (int hf = 0; hf < 2; hf++) {
                    int j = np * 2 + hf;
                    mma_bf16(sc[j], aqh, &kbh[np][hf * 2]);
                    mma_bf16(sc[j], aqh, &kbl[np][hf * 2]);
                    mma_bf16(sc[j], aql, &kbh[np][hf * 2]);
                }
        }

        if ((t + 1) * 64 > n_keys) {
            int cb = t * 64 + (lane & 3) * 2;
#pragma unroll
            for (int j = 0; j < 8; j++)
#pragma unroll
                for (int ii = 0; ii < 2; ii++) {
                    if (cb + j * 8 + ii >= n_keys) { sc[j][ii] = -1e30f; sc[j][2 + ii] = -1e30f; }
                }
        }

        // ---- online softmax on fragments ----
        float mx0 = -1e30f, mx1 = -1e30f;
#pragma unroll
        for (int j = 0; j < 8; j++) {
            mx0 = fmaxf(mx0, fmaxf(sc[j][0], sc[j][1]));
            mx1 = fmaxf(mx1, fmaxf(sc[j][2], sc[j][3]));
        }
        mx0 = fmaxf(mx0, __shfl_xor_sync(0xffffffffu, mx0, 1));
        mx0 = fmaxf(mx0, __shfl_xor_sync(0xffffffffu, mx0, 2));
        mx1 = fmaxf(mx1, __shfl_xor_sync(0xffffffffu, mx1, 1));
        mx1 = fmaxf(mx1, __shfl_xor_sync(0xffffffffu, mx1, 2));
        float mn0 = fmaxf(m0, mx0), mn1 = fmaxf(m1, mx1);
        float c0 = __expf(m0 - mn0), c1 = __expf(m1 - mn1);
        m0 = mn0; m1 = mn1;
        float s0 = 0.f, s1 = 0.f;
#pragma unroll
        for (int j = 0; j < 8; j++) {
            sc[j][0] = __expf(sc[j][0] - mn0); s0 += sc[j][0];
            sc[j][1] = __expf(sc[j][1] - mn0); s0 += sc[j][1];
            sc[j][2] = __expf(sc[j][2] - mn1); s1 += sc[j][2];
            sc[j][3] = __expf(sc[j][3] - mn1); s1 += sc[j][3];
        }
        s0 += __shfl_xor_sync(0xffffffffu, s0, 1);
        s0 += __shfl_xor_sync(0xffffffffu, s0, 2);
        s1 += __shfl_xor_sync(0xffffffffu, s1, 1);
        s1 += __shfl_xor_sync(0xffffffffu, s1, 2);
        l0 = l0 * c0 + s0;
        l1 = l1 * c1 + s1;
#pragma unroll
        for (int j = 0; j < 8; j++) {
            o[j][0] *= c0; o[j][1] *= c0; o[j][2] *= c1; o[j][3] *= c1;
        }

        // ---- P @ V (split P in regs; V via ldmatrix.trans) ----
#pragma unroll
        for (int ks = 0; ks < 4; ks++) {
            uint32_t pah[4], pal[4];
            split2(sc[2 * ks][0],     sc[2 * ks][1],     pah[0], pal[0]);
            split2(sc[2 * ks][2],     sc[2 * ks][3],     pah[1], pal[1]);
            split2(sc[2 * ks + 1][0], sc[2 * ks + 1][1], pah[2], pal[2]);
            split2(sc[2 * ks + 1][2], sc[2 * ks + 1][3], pah[3], pal[3]);
#pragma unroll
            for (int dp = 0; dp < 4; dp++) {
                uint32_t vbh[4], vbl[4];
                uint32_t ad = bb + VH_O + (uint32_t)((ks * 16 + t_row) * ROWQ + (dp * 16 + t_col) * 2);
                ldsm4t(vbh, ad);
                ldsm4t(vbl, ad + (VL_O - VH_O));
                mma_bf16(o[dp * 2],     pah, &vbh[0]);
                mma_bf16(o[dp * 2],     pah, &vbl[0]);
                mma_bf16(o[dp * 2],     pal, &vbh[0]);
                mma_bf16(o[dp * 2 + 1], pah, &vbh[2]);
                mma_bf16(o[dp * 2 + 1], pah, &vbl[2]);
                mma_bf16(o[dp * 2 + 1], pal, &vbh[2]);
            }
        }
    }

    // ---- epilogue ----
    const float inv0 = 1.f / l0, inv1 = 1.f / l1;
    const int rq = wm + (lane >> 2);
    const int cb = (lane & 3) * 2;
    if (!do_ln) {
#pragma unroll
        for (int j = 0; j < 8; j++) {
            *(float2*)(outp + (size_t)rq * 64 + j * 8 + cb) =
                make_float2(o[j][0] * inv0, o[j][1] * inv0);
            *(float2*)(outp + (size_t)(rq + 8) * 64 + j * 8 + cb) =
                make_float2(o[j][2] * inv1, o[j][3] * inv1);
        }
    } else {
        float v0[8][2], v1[8][2];
        float sum0 = 0.f, sum1 = 0.f;
#pragma unroll
        for (int j = 0; j < 8; j++) {
            v0[j][0] = o[j][0] * inv0; v0[j][1] = o[j][1] * inv0;
            v1[j][0] = o[j][2] * inv1; v1[j][1] = o[j][3] * inv1;
            sum0 += v0[j][0] + v0[j][1];
            sum1 += v1[j][0] + v1[j][1];
        }
        sum0 += __shfl_xor_sync(0xffffffffu, sum0, 1);
        sum0 += __shfl_xor_sync(0xffffffffu, sum0, 2);
        sum1 += __shfl_xor_sync(0xffffffffu, sum1, 1);
        sum1 += __shfl_xor_sync(0xffffffffu, sum1, 2);
        float mu0 = sum0 * (1.f / 64.f), mu1 = sum1 * (1.f / 64.f);
        float var0 = 0.f, var1 = 0.f;
#pragma unroll
        for (int j = 0; j < 8; j++) {
            float a0 = v0[j][0] - mu0, a1 = v0[j][1] - mu0;
            float b0 = v1[j][0] - mu1, b1 = v1[j][1] - mu1;
            var0 += a0 * a0 + a1 * a1;
            var1 += b0 * b0 + b1 * b1;
        }
        var0 += __shfl_xor_sync(0xffffffffu, var0, 1);
        var0 += __shfl_xor_sync(0xffffffffu, var0, 2);
        var1 += __shfl_xor_sync(0xffffffffu, var1, 1);
        var1 += __shfl_xor_sync(0xffffffffu, var1, 2);
        float is0 = rsqrtf(var0 * (1.f / 64.f) + 1e-5f);
        float is1 = rsqrtf(var1 * (1.f / 64.f) + 1e-5f);
#pragma unroll
        for (int j = 0; j < 8; j++) {
            int col = j * 8 + cb;
            float g0 = gamma[col], g1 = gamma[col + 1];
            float be0 = beta[col], be1 = beta[col + 1];
            *(float2*)(outp + (size_t)rq * 64 + col) =
                make_float2((v0[j][0] - mu0) * is0 * g0 + be0,
                            (v0[j][1] - mu0) * is0 * g1 + be1);
            *(float2*)(outp + (size_t)(rq + 8) * 64 + col) =
                make_float2((v1[j][0] - mu1) * is1 * g0 + be0,
                            (v1[j][1] - mu1) * is1 * g1 + be1);
        }
    }
}

// ---------------- gate: sigmoid([local, global] @ Wg + bg), fuse, write split bf16 ----------------
__global__ void gate_kernel(const float* __restrict__ Wg,
                            const float* __restrict__ bg) {
    __shared__ float Wgs[128 * 64];
    __shared__ float sloc[4][64];
    __shared__ float sglob[4][64];

    const int tid = threadIdx.x;
    for (int i = tid; i < 128 * 64; i += 256) Wgs[i] = Wg[i];

    const int r0 = blockIdx.x * 4;
    const int rs = tid >> 6;
    const int j  = tid & 63;
    const int r  = r0 + rs;

    sloc[rs][j]  = g_local[(size_t)r * 64 + j];
    sglob[rs][j] = g_glob[(size_t)r * 64 + j];
    __syncthreads();

    float acc = bg[j];
#pragma unroll 8
    for (int k = 0; k < 64; k++)
        acc += sloc[rs][k] * Wgs[k * 64 + j] + sglob[rs][k] * Wgs[(64 + k) * 64 + j];

    float g = 1.f / (1.f + __expf(-acc));
    float fused = g * sloc[rs][j] + (1.f - g) * sglob[rs][j];

    int bb = r / (H_ * S_);
    int h  = (r / S_) % H_;
    int ss = r % S_;
    size_t o = ((size_t)bb * S_ + ss) * D_ + h * DH_ + j;
    __nv_bfloat16 hv = __float2bfloat16(fused);
    g_Fh[o] = hv;
    g_Fl[o] = __float2bfloat16(fused - __bfloat162float(hv));
}

// ---------------- launch ----------------
extern "C" void kernel_launch(void* const* d_in, const int* in_sizes, int n_in,
                              void* d_out, int out_size) {
    (void)in_sizes; (void)n_in; (void)out_size;
    const float* x   = (const float*)d_in[0];
    const float* Wq  = (const float*)d_in[1];
    const float* Wk  = (const float*)d_in[2];
    const float* Wv  = (const float*)d_in[3];
    const float* Wo  = (const float*)d_in[4];
    const float* bo  = (const float*)d_in[5];
    const float* gam = (const float*)d_in[6];
    const float* bet = (const float*)d_in[7];
    const float* Wg  = (const float*)d_in[8];
    const float* bg  = (const float*)d_in[9];
    float* out = (float*)d_out;

    cudaFuncSetAttribute(gemm_bf16, cudaFuncAttributeMaxDynamicSharedMemorySize, GEMM2_SMEM);
    cudaFuncSetAttribute(flash_mma, cudaFuncAttributeMaxDynamicSharedMemorySize, FLM_SMEM);

    __nv_bfloat16 *kh, *kl, *vh, *vl, *kgh, *kgl, *vgh, *vgl, *xh, *xl, *fh, *fl;
    float *lo, *gl;
    cudaGetSymbolAddress((void**)&kh,  g_Kh);
    cudaGetSymbolAddress((void**)&kl,  g_Kl);
    cudaGetSymbolAddress((void**)&vh,  g_Vh);
    cudaGetSymbolAddress((void**)&vl,  g_Vl);
    cudaGetSymbolAddress((void**)&kgh, g_Kgh);
    cudaGetSymbolAddress((void**)&kgl, g_Kgl);
    cudaGetSymbolAddress((void**)&vgh, g_Vgh);
    cudaGetSymbolAddress((void**)&vgl, g_Vgl);
    cudaGetSymbolAddress((void**)&xh,  g_Xh);
    cudaGetSymbolAddress((void**)&xl,  g_Xl);
    cudaGetSymbolAddress((void**)&fh,  g_Fh);
    cudaGetSymbolAddress((void**)&fl,  g_Fl);
    cudaGetSymbolAddress((void**)&lo,  g_local);
    cudaGetSymbolAddress((void**)&gl,  g_glob);

    conv_x<<<(B_ * S_ * D_) / 1024, 256>>>(x);
    conv_wt<<<dim3(32, 32, 4), dim3(32, 8)>>>(Wq, Wk, Wv, Wo);
    gemm_bf16<<<dim3(16, 32, 3), 256, GEMM2_SMEM>>>(xh, xl, nullptr, nullptr, 0);
    topk_kernel<<<B_ * H_, 1024>>>();
    gather_kernel<<<B_ * H_, 256>>>();
    flash_mma<<<dim3(S_ / 128, B_ * H_), 256, FLM_SMEM>>>(
        kh, kl, vh, vl, (size_t)S_ * 64, S_, S_ / 64, lo, gam, bet, 0);
    flash_mma<<<dim3(S_ / 128, B_ * H_), 256, FLM_SMEM>>>(
        kgh, kgl, vgh, vgl, (size_t)256 * 64, NG_, 4, gl, gam, bet, 1);
    gate_kernel<<<(B_ * H_ * S_) / 4, 256>>>(Wg, bg);
    gemm_bf16<<<dim3(16, 32, 1), 256, GEMM2_SMEM>>>(fh, fl, bo, out, 1);
}

// round 8
// speedup vs baseline: 4.8763x; 1.1762x over previous
#include <cuda_runtime.h>
#include <cuda_bf16.h>
#include <cstdint>

#define B_ 2
#define S_ 2048
#define D_ 1024
#define H_ 16
#define DH_ 64
#define NG_ 204
#define SCALE_ 0.125f

// ---------------- scratch (static device globals; no allocations) ----------------
__device__ __nv_bfloat16 g_Qh[B_ * H_ * S_ * DH_];  // [bh][s][d], pre-scaled by SCALE_
__device__ __nv_bfloat16 g_Ql[B_ * H_ * S_ * DH_];
__device__ __nv_bfloat16 g_Kh[B_ * H_ * S_ * DH_];
__device__ __nv_bfloat16 g_Kl[B_ * H_ * S_ * DH_];
__device__ __nv_bfloat16 g_Vh[B_ * H_ * S_ * DH_];
__device__ __nv_bfloat16 g_Vl[B_ * H_ * S_ * DH_];
__device__ __nv_bfloat16 g_Kgh[B_ * H_ * 256 * DH_];  // gathered, zero-padded
__device__ __nv_bfloat16 g_Kgl[B_ * H_ * 256 * DH_];
__device__ __nv_bfloat16 g_Vgh[B_ * H_ * 256 * DH_];
__device__ __nv_bfloat16 g_Vgl[B_ * H_ * 256 * DH_];
__device__ __nv_bfloat16 g_Xh[B_ * S_ * D_];          // split input x
__device__ __nv_bfloat16 g_Xl[B_ * S_ * D_];
__device__ __nv_bfloat16 g_Fh[B_ * S_ * D_];          // split fused (gate output)
__device__ __nv_bfloat16 g_Fl[B_ * S_ * D_];
__device__ __nv_bfloat16 g_Wth[4 * D_ * D_];          // W^T [z][n][k] split
__device__ __nv_bfloat16 g_Wtl[4 * D_ * D_];
__device__ __nv_bfloat16 g_Wgth[128 * 64];            // Wg^T [n=64][k=128] split
__device__ __nv_bfloat16 g_Wgtl[128 * 64];
__device__ __nv_bfloat16 g_cath[(size_t)B_ * H_ * S_ * 128];  // [row][local 64 | global 64]
__device__ __nv_bfloat16 g_catl[(size_t)B_ * H_ * S_ * 128];

// ================= mma.sync helpers =================
__device__ __forceinline__ void mma_bf16(float* c, const uint32_t* a, const uint32_t* b) {
    asm volatile(
        "mma.sync.aligned.m16n8k16.row.col.f32.bf16.bf16.f32 "
        "{%0,%1,%2,%3}, {%4,%5,%6,%7}, {%8,%9}, {%0,%1,%2,%3};"
        : "+f"(c[0]), "+f"(c[1]), "+f"(c[2]), "+f"(c[3])
        : "r"(a[0]), "r"(a[1]), "r"(a[2]), "r"(a[3]), "r"(b[0]), "r"(b[1]));
}
__device__ __forceinline__ void ldsm4(uint32_t* r, uint32_t addr) {
    asm volatile("ldmatrix.sync.aligned.m8n8.x4.shared.b16 {%0,%1,%2,%3}, [%4];"
                 : "=r"(r[0]), "=r"(r[1]), "=r"(r[2]), "=r"(r[3]) : "r"(addr));
}
__device__ __forceinline__ void ldsm4t(uint32_t* r, uint32_t addr) {
    asm volatile("ldmatrix.sync.aligned.m8n8.x4.trans.shared.b16 {%0,%1,%2,%3}, [%4];"
                 : "=r"(r[0]), "=r"(r[1]), "=r"(r[2]), "=r"(r[3]) : "r"(addr));
}
__device__ __forceinline__ void cp16(uint32_t dst, const void* src) {
    asm volatile("cp.async.cg.shared.global [%0], [%1], 16;" :: "r"(dst), "l"(src));
}
__device__ __forceinline__ void cp_commit() { asm volatile("cp.async.commit_group;"); }
__device__ __forceinline__ void cp_wait0()  { asm volatile("cp.async.wait_group 0;"); }

__device__ __forceinline__ void split2(float x0, float x1, uint32_t& hi, uint32_t& lo) {
    __nv_bfloat16 h0 = __float2bfloat16(x0);
    __nv_bfloat16 h1 = __float2bfloat16(x1);
    float r0 = x0 - __bfloat162float(h0);
    float r1 = x1 - __bfloat162float(h1);
    __nv_bfloat162 Hh = __halves2bfloat162(h0, h1);
    __nv_bfloat162 Ll = __halves2bfloat162(__float2bfloat16(r0), __float2bfloat16(r1));
    hi = *reinterpret_cast<uint32_t*>(&Hh);
    lo = *reinterpret_cast<uint32_t*>(&Ll);
}

// ================= pre-conversion kernels =================
__global__ void conv_x(const float* __restrict__ x) {
    int idx = blockIdx.x * 256 + threadIdx.x;
    float4 v = *(const float4*)(x + (size_t)idx * 4);
    uint32_t h0, l0, h1, l1;
    split2(v.x, v.y, h0, l0);
    split2(v.z, v.w, h1, l1);
    *(uint2*)(g_Xh + (size_t)idx * 4) = make_uint2(h0, h1);
    *(uint2*)(g_Xl + (size_t)idx * 4) = make_uint2(l0, l1);
}

__global__ void conv_wt(const float* __restrict__ W0, const float* __restrict__ W1,
                        const float* __restrict__ W2, const float* __restrict__ W3) {
    __shared__ float t[32][33];
    const int z = blockIdx.z;
    const float* W = (z == 0) ? W0 : (z == 1) ? W1 : (z == 2) ? W2 : W3;
    const int n0 = blockIdx.x * 32, k0 = blockIdx.y * 32;
    const int tx = threadIdx.x, ty = threadIdx.y;
#pragma unroll
    for (int i = 0; i < 4; i++)
        t[ty + i * 8][tx] = W[(size_t)(k0 + ty + i * 8) * D_ + n0 + tx];
    __syncthreads();
    size_t ob = (size_t)z * D_ * D_;
#pragma unroll
    for (int i = 0; i < 4; i++) {
        float v = t[tx][ty + i * 8];
        __nv_bfloat16 h = __float2bfloat16(v);
        __nv_bfloat16 l = __float2bfloat16(v - __bfloat162float(h));
        size_t o = ob + (size_t)(n0 + ty + i * 8) * D_ + k0 + tx;
        g_Wth[o] = h;
        g_Wtl[o] = l;
    }
}

__global__ void conv_wg(const float* __restrict__ Wg) {
    int t = blockIdx.x * 256 + threadIdx.x;   // 8192 elements
    int k = t >> 6, n = t & 63;
    float v = Wg[t];
    __nv_bfloat16 h = __float2bfloat16(v);
    g_Wgth[n * 128 + k] = h;
    g_Wgtl[n * 128 + k] = __float2bfloat16(v - __bfloat162float(h));
}

// ================= bf16-split mma GEMM (pre-split inputs, cp.async 2-stage) =================
#define G2R 144
#define G2_AH 0
#define G2_AL 18432
#define G2_BH 36864
#define G2_BL 46080
#define G2_STG 55296
#define GEMM2_SMEM 110592
#define CSP 66

__global__ void __launch_bounds__(256, 2)
gemm_bf16(const __nv_bfloat16* __restrict__ Ah, const __nv_bfloat16* __restrict__ Al,
          const float* __restrict__ bias, float* __restrict__ outp, int is_out) {
    extern __shared__ char smc[];
    const uint32_t smb = (uint32_t)__cvta_generic_to_shared(smc);
    float* Cs = (float*)smc;

    const int tid = threadIdx.x;
    const int wid = tid >> 5;
    const int lane = tid & 31;
    const int n0 = blockIdx.x * 64;
    const int m0 = blockIdx.y * 128;
    const int z = blockIdx.z;
    const size_t woff = (size_t)(is_out ? 3 : z) * D_ * D_;

    const int warp_m0 = (wid & 3) * 32;
    const int warp_n0 = (wid >> 2) * 32;

    auto stage = [&](int ch) {
        uint32_t sb = smb + (uint32_t)(ch & 1) * G2_STG;
        const int K0 = ch * 64;
#pragma unroll
        for (int i = 0; i < 8; i++) {
            int e = tid + i * 256;
            int half = e >> 10, r = (e >> 3) & 127, c = e & 7;
            const __nv_bfloat16* src = (half ? Al : Ah) + (size_t)(m0 + r) * D_ + K0 + c * 8;
            cp16(sb + (half ? G2_AL : G2_AH) + r * G2R + c * 16, src);
        }
#pragma unroll
        for (int i = 0; i < 4; i++) {
            int e = tid + i * 256;
            int half = e >> 9, n = (e >> 3) & 63, c = e & 7;
            const __nv_bfloat16* src = (half ? g_Wtl : g_Wth) + woff +
                                       (size_t)(n0 + n) * D_ + K0 + c * 8;
            cp16(sb + (half ? G2_BL : G2_BH) + n * G2R + c * 16, src);
        }
        cp_commit();
    };

    float acc[2][4][4] = {};

    const int lrm = lane & 7;
    const int lmat = lane >> 3;
    const int a_row = lrm + (lmat & 1) * 8;
    const int a_koff = (lmat >> 1) * 16;
    const int b_row = lrm + (lmat >> 1) * 8;
    const int b_koff = (lmat & 1) * 16;

    stage(0);
    for (int ch = 0; ch < 16; ch++) {
        cp_wait0();
        __syncthreads();
        if (ch + 1 < 16) stage(ch + 1);
        const uint32_t sb = smb + (uint32_t)(ch & 1) * G2_STG;

#pragma unroll
        for (int ks = 0; ks < 4; ks++) {
            uint32_t ah[2][4], al[2][4], bh[2][4], bl[2][4];
#pragma unroll
            for (int mt = 0; mt < 2; mt++) {
                uint32_t ad = sb + G2_AH + (uint32_t)((warp_m0 + mt * 16 + a_row) * G2R + ks * 32 + a_koff);
                ldsm4(ah[mt], ad);
                ldsm4(al[mt], ad + (G2_AL - G2_AH));
            }
#pragma unroll
            for (int np = 0; np < 2; np++) {
                uint32_t ad = sb + G2_BH + (uint32_t)((warp_n0 + np * 16 + b_row) * G2R + ks * 32 + b_koff);
                ldsm4(bh[np], ad);
                ldsm4(bl[np], ad + (G2_BL - G2_BH));
            }
#pragma unroll
            for (int mt = 0; mt < 2; mt++)
#pragma unroll
                for (int nt = 0; nt < 4; nt++) {
                    const uint32_t* Bh = &bh[nt >> 1][(nt & 1) * 2];
                    const uint32_t* Bl = &bl[nt >> 1][(nt & 1) * 2];
                    mma_bf16(acc[mt][nt], ah[mt], Bh);
                    mma_bf16(acc[mt][nt], ah[mt], Bl);
                    mma_bf16(acc[mt][nt], al[mt], Bh);
                }
        }
        __syncthreads();
    }

#pragma unroll
    for (int mt = 0; mt < 2; mt++)
#pragma unroll
        for (int nt = 0; nt < 4; nt++) {
            int r = warp_m0 + mt * 16 + (lane >> 2);
            int c = warp_n0 + nt * 8 + (lane & 3) * 2;
            Cs[r * CSP + c]           = acc[mt][nt][0];
            Cs[r * CSP + c + 1]       = acc[mt][nt][1];
            Cs[(r + 8) * CSP + c]     = acc[mt][nt][2];
            Cs[(r + 8) * CSP + c + 1] = acc[mt][nt][3];
        }
    __syncthreads();

    const int bb = m0 >> 11;
    const int s0 = m0 & 2047;
    const int h = n0 >> 6;
    if (is_out) {
        for (int e = tid; e < 8192; e += 256) {
            int sl = e >> 6, d = e & 63;
            outp[(size_t)(m0 + sl) * D_ + n0 + d] = Cs[sl * CSP + d] + bias[n0 + d];
        }
    } else {
        __nv_bfloat16 *dh, *dl;
        if (z == 0)      { dh = g_Qh; dl = g_Ql; }
        else if (z == 1) { dh = g_Kh; dl = g_Kl; }
        else             { dh = g_Vh; dl = g_Vl; }
        const float sc = (z == 0) ? SCALE_ : 1.f;
        size_t base = ((size_t)(bb * H_ + h) * S_ + s0) * 64;
        for (int e = tid; e < 8192; e += 256) {
            int sl = e >> 6, d = e & 63;
            float x = Cs[sl * CSP + d] * sc;
            __nv_bfloat16 hv = __float2bfloat16(x);
            __nv_bfloat16 lv = __float2bfloat16(x - __bfloat162float(hv));
            dh[base + (size_t)sl * 64 + d] = hv;
            dl[base + (size_t)sl * 64 + d] = lv;
        }
    }
}

// ---------------- top-k (radix select) + gather, one block per (b,h) ----------------
__global__ void __launch_bounds__(512) topk_gather() {
    __shared__ uint32_t bits[S_];
    __shared__ uint32_t hist[256];
    __shared__ int sel[256];
    __shared__ uint32_t bc[2];     // chosen digit, k_rem
    __shared__ uint32_t cnt, eqc;

    const int bh = blockIdx.x;
    const int tid = threadIdx.x;

    for (int s = tid; s < S_; s += 512) {
        const __nv_bfloat162* kh = (const __nv_bfloat162*)(g_Kh + ((size_t)bh * S_ + s) * 64);
        const __nv_bfloat162* kl = (const __nv_bfloat162*)(g_Kl + ((size_t)bh * S_ + s) * 64);
        float sum = 0.f;
#pragma unroll 8
        for (int d = 0; d < 32; d++) {
            float2 h2 = __bfloat1622float2(kh[d]);
            float2 l2 = __bfloat1622float2(kl[d]);
            float v0 = h2.x + l2.x, v1 = h2.y + l2.y;
            sum += v0 * v0 + v1 * v1;
        }
        bits[s] = __float_as_uint(sum);   // non-negative floats order as uints
    }
    if (tid == 0) { cnt = 0; eqc = 0; }
    if (tid >= 204 && tid < 256) sel[tid] = -1;
    __syncthreads();

    uint32_t prefix = 0, pmask = 0, k_rem = NG_;
#pragma unroll
    for (int level = 3; level >= 0; level--) {
        const int sh = level * 8;
        if (tid < 256) hist[tid] = 0;
        __syncthreads();
        for (int s = tid; s < S_; s += 512) {
            uint32_t v = bits[s];
            if ((v & pmask) == prefix)
                atomicAdd(&hist[(v >> sh) & 255], 1u);
        }
        __syncthreads();
        if (tid < 32) {
            const int base = tid * 8;
            uint32_t tot = 0;
#pragma unroll
            for (int i = 0; i < 8; i++) tot += hist[base + i];
            uint32_t suf = tot;
#pragma unroll
            for (int off = 1; off < 32; off <<= 1) {
                uint32_t t = __shfl_down_sync(0xffffffffu, suf, off);
                if (tid + off < 32) suf += t;
            }
            uint32_t suf_excl = suf - tot;
            if (suf_excl < k_rem && k_rem <= suf) {
                uint32_t cum = suf_excl;
                for (int i = 7; i >= 0; i--) {
                    cum += hist[base + i];
                    if (cum >= k_rem) {
                        bc[0] = (uint32_t)(base + i);
                        bc[1] = k_rem - (cum - hist[base + i]);
                        break;
                    }
                }
            }
        }
        __syncthreads();
        prefix |= bc[0] << sh;
        pmask  |= 255u << sh;
        k_rem = bc[1];
        __syncthreads();
    }

    const uint32_t T = prefix;      // exact threshold value; k_rem == count of ties to keep
    for (int s = tid; s < S_; s += 512) {
        uint32_t v = bits[s];
        if (v > T) {
            int p = atomicAdd(&cnt, 1u);
            sel[p] = s;
        } else if (v == T) {
            uint32_t e = atomicAdd(&eqc, 1u);
            if (e < k_rem) {
                int p = atomicAdd(&cnt, 1u);
                sel[p] = s;
            }
        }
    }
    __syncthreads();

    // gather K/V hi/lo (zero-pad rows 204..255)
    const size_t sb = (size_t)bh * S_ * 64;
    const size_t gb = (size_t)bh * 256 * 64;
    const uint4 zero = make_uint4(0, 0, 0, 0);
    for (int e = tid; e < 2048; e += 512) {
        int g = e >> 3, c = e & 7;
        int k = sel[g];
        size_t so = sb + (size_t)k * 64 + c * 8;
        size_t go = gb + (size_t)g * 64 + c * 8;
        *(uint4*)(g_Kgh + go) = (k >= 0) ? *(const uint4*)(g_Kh + so) : zero;
        *(uint4*)(g_Kgl + go) = (k >= 0) ? *(const uint4*)(g_Kl + so) : zero;
        *(uint4*)(g_Vgh + go) = (k >= 0) ? *(const uint4*)(g_Vh + so) : zero;
        *(uint4*)(g_Vgl + go) = (k >= 0) ? *(const uint4*)(g_Vl + so) : zero;
    }
}

// ================= flash attention via mma.sync (bf16 split) =================
#define ROWQ 144
#define QH_OFF 0
#define QL_OFF 18432
#define KV0 36864
#define KVSZ 36864
#define KH_O 0
#define KL_O 9216
#define VH_O 18432
#define VL_O 27648
#define FLM_SMEM 110592

__global__ void __launch_bounds__(256, 2) flash_mma(
    const __nv_bfloat16* __restrict__ Kh, const __nv_bfloat16* __restrict__ Kl,
    const __nv_bfloat16* __restrict__ Vh, const __nv_bfloat16* __restrict__ Vl,
    size_t kv_stride, int n_keys, int n_tiles,
    const float* __restrict__ gamma, const float* __restrict__ beta,
    int do_ln, int cat_off) {
    extern __shared__ char smc[];
    const uint32_t smb = (uint32_t)__cvta_generic_to_shared(smc);
    const int tid = threadIdx.x;
    const int wid = tid >> 5;
    const int lane = tid & 31;
    const int bh = blockIdx.y;
    const int q0 = blockIdx.x * 128;

    const __nv_bfloat16* Qh = g_Qh + ((size_t)bh * S_ + q0) * 64;
    const __nv_bfloat16* Ql = g_Ql + ((size_t)bh * S_ + q0) * 64;
    Kh += (size_t)bh * kv_stride;
    Kl += (size_t)bh * kv_stride;
    Vh += (size_t)bh * kv_stride;
    Vl += (size_t)bh * kv_stride;
    __nv_bfloat16* cath = g_cath + ((size_t)bh * S_ + q0) * 128 + cat_off;
    __nv_bfloat16* catl = g_catl + ((size_t)bh * S_ + q0) * 128 + cat_off;

    const __nv_bfloat16* srcs[4] = {Kh, Kl, Vh, Vl};
    auto stage_tile = [&](int t, int bsel) {
        uint32_t dstb = smb + KV0 + bsel * KVSZ;
#pragma unroll
        for (int i = 0; i < 8; i++) {
            int e = tid + i * 256;
            int arr = e >> 9, r = (e >> 3) & 63, c = e & 7;
            cp16(dstb + arr * 9216 + r * ROWQ + c * 16,
                 srcs[arr] + (size_t)(t * 64 + r) * 64 + c * 8);
        }
        cp_commit();
    };
    stage_tile(0, 0);

    for (int e = tid; e < 1024; e += 256) {
        int r = e >> 3, c = e & 7;
        *(uint4*)(smc + QH_OFF + r * ROWQ + c * 16) = *(const uint4*)(Qh + (size_t)r * 64 + c * 8);
        *(uint4*)(smc + QL_OFF + r * ROWQ + c * 16) = *(const uint4*)(Ql + (size_t)r * 64 + c * 8);
    }
    __syncthreads();

    const int lrm = lane & 7;
    const int lmat = lane >> 3;
    const int a_row = lrm + (lmat & 1) * 8;
    const int a_koff = (lmat >> 1) * 16;
    const int b_row = lrm + (lmat >> 1) * 8;
    const int b_koff = (lmat & 1) * 16;
    const int t_row = lrm + (lmat & 1) * 8;
    const int t_col = (lmat >> 1) * 8;
    const int wm = wid * 16;

    float o[8][4] = {};
    float m0 = -1e30f, m1 = -1e30f, l0 = 0.f, l1 = 0.f;

    for (int t = 0; t < n_tiles; t++) {
        cp_wait0();
        __syncthreads();
        if (t + 1 < n_tiles) stage_tile(t + 1, (t + 1) & 1);
        const uint32_t bb = smb + KV0 + (uint32_t)(t & 1) * KVSZ;

        float sc[8][4] = {};
#pragma unroll
        for (int ks = 0; ks < 4; ks++) {
            uint32_t aqh[4], aql[4];
            uint32_t qa = smb + QH_OFF + (uint32_t)((wm + a_row) * ROWQ + ks * 32 + a_koff);
            ldsm4(aqh, qa);
            ldsm4(aql, qa + (QL_OFF - QH_OFF));
            uint32_t kbh[4][4], kbl[4][4];
#pragma unroll
            for (int np = 0; np < 4; np++) {
                uint32_t ad = bb + KH_O + (uint32_t)((np * 16 + b_row) * ROWQ + ks * 32 + b_koff);
                ldsm4(kbh[np], ad);
                ldsm4(kbl[np], ad + (KL_O - KH_O));
            }
#pragma unroll
            for (int np = 0; np < 4; np++)
#pragma unroll
                for (int hf = 0; hf < 2; hf++) {
                    int j = np * 2 + hf;
                    mma_bf16(sc[j], aqh, &kbh[np][hf * 2]);
                    mma_bf16(sc[j], aqh, &kbl[np][hf * 2]);
                    mma_bf16(sc[j], aql, &kbh[np][hf * 2]);
                }
        }

        if ((t + 1) * 64 > n_keys) {
            int cb2 = t * 64 + (lane & 3) * 2;
#pragma unroll
            for (int j = 0; j < 8; j++)
#pragma unroll
                for (int ii = 0; ii < 2; ii++) {
                    if (cb2 + j * 8 + ii >= n_keys) { sc[j][ii] = -1e30f; sc[j][2 + ii] = -1e30f; }
                }
        }

        float mx0 = -1e30f, mx1 = -1e30f;
#pragma unroll
        for (int j = 0; j < 8; j++) {
            mx0 = fmaxf(mx0, fmaxf(sc[j][0], sc[j][1]));
            mx1 = fmaxf(mx1, fmaxf(sc[j][2], sc[j][3]));
        }
        mx0 = fmaxf(mx0, __shfl_xor_sync(0xffffffffu, mx0, 1));
        mx0 = fmaxf(mx0, __shfl_xor_sync(0xffffffffu, mx0, 2));
        mx1 = fmaxf(mx1, __shfl_xor_sync(0xffffffffu, mx1, 1));
        mx1 = fmaxf(mx1, __shfl_xor_sync(0xffffffffu, mx1, 2));
        float mn0 = fmaxf(m0, mx0), mn1 = fmaxf(m1, mx1);
        float c0 = __expf(m0 - mn0), c1 = __expf(m1 - mn1);
        m0 = mn0; m1 = mn1;
        float s0 = 0.f, s1 = 0.f;
#pragma unroll
        for (int j = 0; j < 8; j++) {
            sc[j][0] = __expf(sc[j][0] - mn0); s0 += sc[j][0];
            sc[j][1] = __expf(sc[j][1] - mn0); s0 += sc[j][1];
            sc[j][2] = __expf(sc[j][2] - mn1); s1 += sc[j][2];
            sc[j][3] = __expf(sc[j][3] - mn1); s1 += sc[j][3];
        }
        s0 += __shfl_xor_sync(0xffffffffu, s0, 1);
        s0 += __shfl_xor_sync(0xffffffffu, s0, 2);
        s1 += __shfl_xor_sync(0xffffffffu, s1, 1);
        s1 += __shfl_xor_sync(0xffffffffu, s1, 2);
        l0 = l0 * c0 + s0;
        l1 = l1 * c1 + s1;
#pragma unroll
        for (int j = 0; j < 8; j++) {
            o[j][0] *= c0; o[j][1] *= c0; o[j][2] *= c1; o[j][3] *= c1;
        }

#pragma unroll
        for (int ks = 0; ks < 4; ks++) {
            uint32_t pah[4], pal[4];
            split2(sc[2 * ks][0],     sc[2 * ks][1],     pah[0], pal[0]);
            split2(sc[2 * ks][2],     sc[2 * ks][3],     pah[1], pal[1]);
            split2(sc[2 * ks + 1][0], sc[2 * ks + 1][1], pah[2], pal[2]);
            split2(sc[2 * ks + 1][2], sc[2 * ks + 1][3], pah[3], pal[3]);
#pragma unroll
            for (int dp = 0; dp < 4; dp++) {
                uint32_t vbh[4], vbl[4];
                uint32_t ad = bb + VH_O + (uint32_t)((ks * 16 + t_row) * ROWQ + (dp * 16 + t_col) * 2);
                ldsm4t(vbh, ad);
                ldsm4t(vbl, ad + (VL_O - VH_O));
                mma_bf16(o[dp * 2],     pah, &vbh[0]);
                mma_bf16(o[dp * 2],     pah, &vbl[0]);
                mma_bf16(o[dp * 2],     pal, &vbh[0]);
                mma_bf16(o[dp * 2 + 1], pah, &vbh[2]);
                mma_bf16(o[dp * 2 + 1], pah, &vbl[2]);
                mma_bf16(o[dp * 2 + 1], pal, &vbh[2]);
            }
        }
    }

    // ---- epilogue: write double-bf16 into cat buffer ----
    const float inv0 = 1.f / l0, inv1 = 1.f / l1;
    const int rq = wm + (lane >> 2);
    const int cb = (lane & 3) * 2;
    float v0[8][2], v1[8][2];
#pragma unroll
    for (int j = 0; j < 8; j++) {
        v0[j][0] = o[j][0] * inv0; v0[j][1] = o[j][1] * inv0;
        v1[j][0] = o[j][2] * inv1; v1[j][1] = o[j][3] * inv1;
    }
    if (do_ln) {
        float sum0 = 0.f, sum1 = 0.f;
#pragma unroll
        for (int j = 0; j < 8; j++) {
            sum0 += v0[j][0] + v0[j][1];
            sum1 += v1[j][0] + v1[j][1];
        }
        sum0 += __shfl_xor_sync(0xffffffffu, sum0, 1);
        sum0 += __shfl_xor_sync(0xffffffffu, sum0, 2);
        sum1 += __shfl_xor_sync(0xffffffffu, sum1, 1);
        sum1 += __shfl_xor_sync(0xffffffffu, sum1, 2);
        float mu0 = sum0 * (1.f / 64.f), mu1 = sum1 * (1.f / 64.f);
        float var0 = 0.f, var1 = 0.f;
#pragma unroll
        for (int j = 0; j < 8; j++) {
            float a0 = v0[j][0] - mu0, a1 = v0[j][1] - mu0;
            float b0 = v1[j][0] - mu1, b1 = v1[j][1] - mu1;
            var0 += a0 * a0 + a1 * a1;
            var1 += b0 * b0 + b1 * b1;
        }
        var0 += __shfl_xor_sync(0xffffffffu, var0, 1);
        var0 += __shfl_xor_sync(0xffffffffu, var0, 2);
        var1 += __shfl_xor_sync(0xffffffffu, var1, 1);
        var1 += __shfl_xor_sync(0xffffffffu, var1, 2);
        float is0 = rsqrtf(var0 * (1.f / 64.f) + 1e-5f);
        float is1 = rsqrtf(var1 * (1.f / 64.f) + 1e-5f);
#pragma unroll
        for (int j = 0; j < 8; j++) {
            int col = j * 8 + cb;
            float g0 = gamma[col], g1 = gamma[col + 1];
            float be0 = beta[col], be1 = beta[col + 1];
            v0[j][0] = (v0[j][0] - mu0) * is0 * g0 + be0;
            v0[j][1] = (v0[j][1] - mu0) * is0 * g1 + be1;
            v1[j][0] = (v1[j][0] - mu1) * is1 * g0 + be0;
            v1[j][1] = (v1[j][1] - mu1) * is1 * g1 + be1;
        }
    }
#pragma unroll
    for (int j = 0; j < 8; j++) {
        int col = j * 8 + cb;
        uint32_t h0, lw0, h1, lw1;
        split2(v0[j][0], v0[j][1], h0, lw0);
        split2(v1[j][0], v1[j][1], h1, lw1);
        *(uint32_t*)(cath + (size_t)rq * 128 + col)       = h0;
        *(uint32_t*)(catl + (size_t)rq * 128 + col)       = lw0;
        *(uint32_t*)(cath + (size_t)(rq + 8) * 128 + col) = h1;
        *(uint32_t*)(catl + (size_t)(rq + 8) * 128 + col) = lw1;
    }
}

// ================= gate via mma: z = cat @ Wg^T(+bg), fuse, write split bf16 =================
#define GR 272
#define GA_H 0
#define GA_L 34816
#define GB_H 69632
#define GB_L 87040
#define GATE_SMEM 104448

__global__ void __launch_bounds__(256, 2)
gate_mma(const float* __restrict__ bg) {
    extern __shared__ char smc[];
    const uint32_t smb = (uint32_t)__cvta_generic_to_shared(smc);
    const int tid = threadIdx.x;
    const int wid = tid >> 5;
    const int lane = tid & 31;
    const int m0 = blockIdx.x * 128;

    // stage A (cat rows) and B (Wgt) h/l
#pragma unroll
    for (int i = 0; i < 16; i++) {
        int e = tid + i * 256;
        int half = e >> 11, r = (e >> 4) & 127, c = e & 15;
        const __nv_bfloat16* src = (half ? g_catl : g_cath) + (size_t)(m0 + r) * 128 + c * 8;
        cp16(smb + (half ? GA_L : GA_H) + r * GR + c * 16, src);
    }
#pragma unroll
    for (int i = 0; i < 8; i++) {
        int e = tid + i * 256;
        int half = e >> 10, r = (e >> 4) & 63, c = e & 15;
        const __nv_bfloat16* src = (half ? g_Wgtl : g_Wgth) + (size_t)r * 128 + c * 8;
        cp16(smb + (half ? GB_L : GB_H) + r * GR + c * 16, src);
    }
    cp_commit();
    cp_wait0();
    __syncthreads();

    const int lrm = lane & 7;
    const int lmat = lane >> 3;
    const int a_row = lrm + (lmat & 1) * 8;
    const int a_koff = (lmat >> 1) * 16;
    const int b_row = lrm + (lmat >> 1) * 8;
    const int b_koff = (lmat & 1) * 16;
    const int wm = wid * 16;

    float acc[8][4] = {};
#pragma unroll
    for (int ks = 0; ks < 8; ks++) {
        uint32_t ah[4], al[4];
        uint32_t aa = smb + GA_H + (uint32_t)((wm + a_row) * GR + ks * 32 + a_koff);
        ldsm4(ah, aa);
        ldsm4(al, aa + (GA_L - GA_H));
        uint32_t bh[4][4], bl[4][4];
#pragma unroll
        for (int np = 0; np < 4; np++) {
            uint32_t ad = smb + GB_H + (uint32_t)((np * 16 + b_row) * GR + ks * 32 + b_koff);
            ldsm4(bh[np], ad);
            ldsm4(bl[np], ad + (GB_L - GB_H));
        }
#pragma unroll
        for (int np = 0; np < 4; np++)
#pragma unroll
            for (int hf = 0; hf < 2; hf++) {
                int j = np * 2 + hf;
                mma_bf16(acc[j], ah, &bh[np][hf * 2]);
                mma_bf16(acc[j], ah, &bl[np][hf * 2]);
                mma_bf16(acc[j], al, &bh[np][hf * 2]);
            }
    }

    // epilogue: sigmoid, mix with loc/glo from staged A, write split g_F
    const int rq = wm + (lane >> 2);
    const int cb = (lane & 3) * 2;
#pragma unroll
    for (int rr = 0; rr < 2; rr++) {
        const int r = rq + rr * 8;
        const int R = m0 + r;
        const int bh = R >> 11;
        const int ss = R & 2047;
        const size_t obase = ((size_t)((bh >> 4) * S_ + ss)) * D_ + (bh & 15) * 64;
#pragma unroll
        for (int j = 0; j < 8; j++) {
            const int col = j * 8 + cb;
            float z0 = acc[j][rr * 2 + 0] + bg[col];
            float z1 = acc[j][rr * 2 + 1] + bg[col + 1];
            float g0 = 1.f / (1.f + __expf(-z0));
            float g1 = 1.f / (1.f + __expf(-z1));
            // loc/glo reconstruct from SMEM (h + l)
            uint32_t lh = *(uint32_t*)(smc + GA_H + r * GR + col * 2);
            uint32_t ll = *(uint32_t*)(smc + GA_L + r * GR + col * 2);
            uint32_t gh = *(uint32_t*)(smc + GA_H + r * GR + (64 + col) * 2);
            uint32_t gl = *(uint32_t*)(smc + GA_L + r * GR + (64 + col) * 2);
            float2 lh2 = __bfloat1622float2(*(__nv_bfloat162*)&lh);
            float2 ll2 = __bfloat1622float2(*(__nv_bfloat162*)&ll);
            float2 gh2 = __bfloat1622float2(*(__nv_bfloat162*)&gh);
            float2 gl2 = __bfloat1622float2(*(__nv_bfloat162*)&gl);
            float loc0 = lh2.x + ll2.x, loc1 = lh2.y + ll2.y;
            float glo0 = gh2.x + gl2.x, glo1 = gh2.y + gl2.y;
            float f0 = g0 * loc0 + (1.f - g0) * glo0;
            float f1 = g1 * loc1 + (1.f - g1) * glo1;
            uint32_t fh, fl;
            split2(f0, f1, fh, fl);
            *(uint32_t*)(g_Fh + obase + col) = fh;
            *(uint32_t*)(g_Fl + obase + col) = fl;
        }
    }
}

// ---------------- launch ----------------
extern "C" void kernel_launch(void* const* d_in, const int* in_sizes, int n_in,
                              void* d_out, int out_size) {
    (void)in_sizes; (void)n_in; (void)out_size;
    const float* x   = (const float*)d_in[0];
    const float* Wq  = (const float*)d_in[1];
    const float* Wk  = (const float*)d_in[2];
    const float* Wv  = (const float*)d_in[3];
    const float* Wo  = (const float*)d_in[4];
    const float* bo  = (const float*)d_in[5];
    const float* gam = (const float*)d_in[6];
    const float* bet = (const float*)d_in[7];
    const float* Wg  = (const float*)d_in[8];
    const float* bg  = (const float*)d_in[9];
    float* out = (float*)d_out;

    cudaFuncSetAttribute(gemm_bf16, cudaFuncAttributeMaxDynamicSharedMemorySize, GEMM2_SMEM);
    cudaFuncSetAttribute(flash_mma, cudaFuncAttributeMaxDynamicSharedMemorySize, FLM_SMEM);
    cudaFuncSetAttribute(gate_mma,  cudaFuncAttributeMaxDynamicSharedMemorySize, GATE_SMEM);

    __nv_bfloat16 *kh, *kl, *vh, *vl, *kgh, *kgl, *vgh, *vgl, *xh, *xl, *fh, *fl;
    cudaGetSymbolAddress((void**)&kh,  g_Kh);
    cudaGetSymbolAddress((void**)&kl,  g_Kl);
    cudaGetSymbolAddress((void**)&vh,  g_Vh);
    cudaGetSymbolAddress((void**)&vl,  g_Vl);
    cudaGetSymbolAddress((void**)&kgh, g_Kgh);
    cudaGetSymbolAddress((void**)&kgl, g_Kgl);
    cudaGetSymbolAddress((void**)&vgh, g_Vgh);
    cudaGetSymbolAddress((void**)&vgl, g_Vgl);
    cudaGetSymbolAddress((void**)&xh,  g_Xh);
    cudaGetSymbolAddress((void**)&xl,  g_Xl);
    cudaGetSymbolAddress((void**)&fh,  g_Fh);
    cudaGetSymbolAddress((void**)&fl,  g_Fl);

    conv_x<<<(B_ * S_ * D_) / 1024, 256>>>(x);
    conv_wt<<<dim3(32, 32, 4), dim3(32, 8)>>>(Wq, Wk, Wv, Wo);
    conv_wg<<<32, 256>>>(Wg);
    gemm_bf16<<<dim3(16, 32, 3), 256, GEMM2_SMEM>>>(xh, xl, nullptr, nullptr, 0);
    topk_gather<<<B_ * H_, 512>>>();
    flash_mma<<<dim3(S_ / 128, B_ * H_), 256, FLM_SMEM>>>(
        kh, kl, vh, vl, (size_t)S_ * 64, S_, S_ / 64, gam, bet, 0, 0);
    flash_mma<<<dim3(S_ / 128, B_ * H_), 256, FLM_SMEM>>>(
        kgh, kgl, vgh, vgl, (size_t)256 * 64, NG_, 4, gam, bet, 1, 64);
    gate_mma<<<(B_ * H_ * S_) / 128, 256, GATE_SMEM>>>(bg);
    gemm_bf16<<<dim3(16, 32, 1), 256, GEMM2_SMEM>>>(fh, fl, bo, out, 1);
}